// round 3
// baseline (speedup 1.0000x reference)
#include <cuda_runtime.h>
#include <cuda_bf16.h>
#include <cstdint>

// ---------------------------------------------------------------------------
// DGCNN segmentation. EdgeConv second linears on tensor cores via mma.sync
// (bf16x3 split precision, base-ISA feature -> compiles at compute_103).
// Node precompute GEMMs + MLP head remain fp32 (proven R1 code).
//
// EdgeConv decomposition:  m = relu([x_i, x_j - x_i] @ W1 + b1) @ W2 + b2
//   per-node AB = [A | B],  A = x@(Wt-Wb)+b1,  B = x@Wb
//   per-edge h = relu(A[dst] + B[src]);  m = h @ W2 + b2;  segment-max(dst)
// ---------------------------------------------------------------------------

#define NMAX 30016
#define EMAX 480256

__device__ float4   g_AB4[NMAX * 512 / 4];
__device__ unsigned g_agg[NMAX * 256];
__device__ float4   g_hcat4[NMAX * 448 / 4];
__device__ float4   g_m14[NMAX * 512 / 4];
__device__ float4   g_m24[NMAX * 256 / 4];
__device__ float    g_wc1[3 * 128];
__device__ float    g_wc2[64 * 256];
__device__ float    g_wc3[128 * 512];
__device__ float    g_bc1[128];
__device__ float    g_bc2[256];
__device__ float    g_bc3[512];
// W2^T hi/lo bf16, [tile][n][Kpad] rows, Kpad = K + 8
__device__ uint4    g_wh1[64 * 72 / 8],       g_wl1[64 * 72 / 8];
__device__ uint4    g_wh2[128 * 136 / 8],     g_wl2[128 * 136 / 8];
__device__ uint4    g_wh3[2 * 128 * 264 / 8], g_wl3[2 * 128 * 264 / 8];
__device__ int      g_src[EMAX];
__device__ int      g_dst[EMAX];
__device__ int      g_is64;

// ---- ordered-uint encoding for float max -----------------------------------
__device__ __forceinline__ unsigned f2ord(float f) {
    int i = __float_as_int(f);
    return (i >= 0) ? ((unsigned)i | 0x80000000u) : ~(unsigned)i;
}
__device__ __forceinline__ float ord2f(unsigned u) {
    int i = (u & 0x80000000u) ? (int)(u & 0x7fffffffu) : (int)(~u);
    return __int_as_float(i);
}

// ---- bf16 mma.sync m16n8k16 (fp32 accum) ------------------------------------
__device__ __forceinline__ void mma_bf16(float* d, const uint32_t* a,
                                         uint32_t b0, uint32_t b1) {
    asm volatile(
        "mma.sync.aligned.m16n8k16.row.col.f32.bf16.bf16.f32 "
        "{%0,%1,%2,%3},{%4,%5,%6,%7},{%8,%9},{%0,%1,%2,%3};"
        : "+f"(d[0]), "+f"(d[1]), "+f"(d[2]), "+f"(d[3])
        : "r"(a[0]), "r"(a[1]), "r"(a[2]), "r"(a[3]), "r"(b0), "r"(b1));
}

// ---- edge_index dtype normalization ----------------------------------------
__global__ void detect_idx_kernel(const unsigned* __restrict__ p, int E) {
    if (threadIdx.x == 0 && blockIdx.x == 0) {
        int n = (E < 256) ? E : 256;
        int is64 = 1;
        for (int i = 0; i < n; i++)
            if (p[2 * i + 1] != 0u) { is64 = 0; break; }
        g_is64 = is64;
    }
}
__global__ void convert_idx_kernel(const void* __restrict__ raw, int E) {
    int i = blockIdx.x * blockDim.x + threadIdx.x;
    if (i >= E) return;
    if (g_is64) {
        const long long* p = (const long long*)raw;
        g_src[i] = (int)p[i];
        g_dst[i] = (int)p[E + i];
    } else {
        const int* p = (const int*)raw;
        g_src[i] = p[i];
        g_dst[i] = p[E + i];
    }
}

// ---- weight prep (fp32 combined first-linear) -------------------------------
__global__ void prep_kernel(const float* __restrict__ w, const float* __restrict__ b,
                            float* __restrict__ wc, float* __restrict__ bc, int C, int H) {
    int stride = gridDim.x * blockDim.x;
    int i0 = blockIdx.x * blockDim.x + threadIdx.x;
    for (int t = i0; t < C * H; t += stride) {
        int k = t / H, j = t % H;
        float wd = w[(k + C) * H + j];
        wc[k * 2 * H + j]     = w[k * H + j] - wd;
        wc[k * 2 * H + H + j] = wd;
    }
    for (int t = i0; t < H; t += stride) { bc[t] = b[t]; bc[H + t] = 0.f; }
}

// ---- weight prep: W2^T hi/lo bf16 into [tile][n][Kpad] ----------------------
__global__ void prep_wb_kernel(const float* __restrict__ W,  // [H, COUT] row-major
                               uint4* __restrict__ Whi, uint4* __restrict__ Wlo,
                               int H, int COUT, int BN) {
    int i = blockIdx.x * blockDim.x + threadIdx.x;
    if (i >= H * COUT) return;
    int k = i / COUT, n = i % COUT;
    int Kpad = H + 8;
    float w = W[i];
    __nv_bfloat16 hb = __float2bfloat16(w);
    __nv_bfloat16 lb = __float2bfloat16(w - __bfloat162float(hb));
    int tile = n / BN, nl = n % BN;
    size_t off = (size_t)tile * BN * Kpad + (size_t)nl * Kpad + k;   // halves
    ((unsigned short*)Whi)[off] = __bfloat16_as_ushort(hb);
    ((unsigned short*)Wlo)[off] = __bfloat16_as_ushort(lb);
}

// ---- layer-1 node precompute: K=3 -------------------------------------------
__global__ void node1_kernel(const float* __restrict__ x, const float* __restrict__ wc,
                             const float* __restrict__ bc, float* __restrict__ AB, int M) {
    int idx = blockIdx.x * blockDim.x + threadIdx.x;
    if (idx >= M * 128) return;
    int n = idx >> 7, j = idx & 127;
    float x0 = x[n * 3 + 0], x1 = x[n * 3 + 1], x2 = x[n * 3 + 2];
    AB[idx] = fmaf(x0, wc[j], fmaf(x1, wc[128 + j], fmaf(x2, wc[256 + j], bc[j])));
}

// ---- fp32 tiled SGEMM (node precompute + MLP head) --------------------------
template <bool RELU>
__global__ void __launch_bounds__(256, 2)
sgemm_bias_kernel(const float* __restrict__ A, int lda,
                  const float* __restrict__ W, int ldw,
                  const float* __restrict__ bias,
                  float* __restrict__ C, int ldc, int M, int N, int K) {
    constexpr int BM = 128, BN = 128, BK = 16;
    __shared__ float As[BK][BM + 4];
    __shared__ float Ws[BK][BN];
    const int tid = threadIdx.x;
    const int bm = blockIdx.x * BM;
    const int bn = blockIdx.y * BN;
    const int rowb = (tid / 16) * 8;
    const int colb = (tid % 16) * 8;
    const int a_m = tid >> 2;
    const int a_k = (tid & 3) * 4;
    const int w_r = tid >> 4;
    const int w_c = (tid & 15) * 8;

    float acc[8][8];
#pragma unroll
    for (int i = 0; i < 8; i++)
#pragma unroll
        for (int j = 0; j < 8; j++) acc[i][j] = 0.f;

    for (int k0 = 0; k0 < K; k0 += BK) {
#pragma unroll
        for (int p = 0; p < 2; p++) {
            int m = a_m + p * 64;
            float4 v = make_float4(0.f, 0.f, 0.f, 0.f);
            if (bm + m < M)
                v = *reinterpret_cast<const float4*>(A + (size_t)(bm + m) * lda + k0 + a_k);
            As[a_k + 0][m] = v.x; As[a_k + 1][m] = v.y;
            As[a_k + 2][m] = v.z; As[a_k + 3][m] = v.w;
        }
#pragma unroll
        for (int q = 0; q < 2; q++)
            *reinterpret_cast<float4*>(&Ws[w_r][w_c + q * 4]) =
                *reinterpret_cast<const float4*>(W + (size_t)(k0 + w_r) * ldw + bn + w_c + q * 4);
        __syncthreads();
#pragma unroll
        for (int kk = 0; kk < BK; kk++) {
            float af[8], wf[8];
#pragma unroll
            for (int i = 0; i < 8; i++) af[i] = As[kk][rowb + i];
#pragma unroll
            for (int j = 0; j < 8; j++) wf[j] = Ws[kk][colb + j];
#pragma unroll
            for (int i = 0; i < 8; i++)
#pragma unroll
                for (int j = 0; j < 8; j++) acc[i][j] = fmaf(af[i], wf[j], acc[i][j]);
        }
        __syncthreads();
    }
#pragma unroll
    for (int i = 0; i < 8; i++) {
        int m = bm + rowb + i;
        if (m >= M) break;
#pragma unroll
        for (int j = 0; j < 8; j++) {
            float v = acc[i][j] + bias[bn + colb + j];
            if (RELU) v = fmaxf(v, 0.f);
            C[(size_t)m * ldc + bn + colb + j] = v;
        }
    }
}

// ---- mma.sync edge kernel ----------------------------------------------------
// Block: 256 thr = 8 warps (4 m x 2 n). Tile: 128 edges x BN outputs, K = H.
// A tile = relu(A[dst]+B[src]) split to bf16 hi/lo, rebuilt per 64-wide K chunk.
// W^T hi/lo resident in SMEM for full K. D = Ah Bh + Al Bh + Ah Bl.
template <int H, int BN>
__global__ void __launch_bounds__(256)
edge_mma_kernel(const float* __restrict__ AB,
                const uint4* __restrict__ Whi_g, const uint4* __restrict__ Wlo_g,
                const float* __restrict__ bias,
                unsigned* __restrict__ agg, int E, int COUT) {
    constexpr int KP   = H + 8;                 // W row pitch (halves)
    constexpr int WB   = BN * KP * 2;           // bytes per W array
    constexpr int AP   = 72;                    // A row pitch (halves) for 64-chunk
    constexpr int ASZ  = 128 * AP * 2;          // bytes per A array (18432)
    constexpr int NA   = BN / 16;               // n-atoms per warp (BN/2 cols / 8)
    constexpr int OWH  = 1024;
    constexpr int OWL  = OWH + WB;
    constexpr int OAH  = OWL + WB;
    constexpr int OAL  = OAH + ASZ;
    constexpr int NCH  = H / 64;

    extern __shared__ char sm[];
    int* sdst = (int*)(sm);
    int* ssrc = (int*)(sm + 512);

    const int tid = threadIdx.x;
    const int wid = tid >> 5, lane = tid & 31;
    const int g = lane >> 2, tig = lane & 3;
    const int e0 = blockIdx.x * 128;
    const int bn = blockIdx.y * BN;

    // ---- load indices + W tile ----
    if (tid < 128) { int e = e0 + tid; ssrc[tid] = (e < E) ? g_src[e] : 0; }
    else           { int e = e0 + tid - 128; sdst[tid - 128] = (e < E) ? g_dst[e] : 0; }
    {
        const int CNT = WB / 16;
        uint4* dh = (uint4*)(sm + OWH);
        uint4* dl = (uint4*)(sm + OWL);
        const uint4* shp = Whi_g + (size_t)blockIdx.y * CNT;
        const uint4* slp = Wlo_g + (size_t)blockIdx.y * CNT;
        for (int i = tid; i < CNT; i += 256) { dh[i] = shp[i]; dl[i] = slp[i]; }
    }
    __syncthreads();

    const int r  = tid >> 1;        // edge row this thread fills
    const int hf = tid & 1;         // which 32-wide half of the 64-chunk
    const float* Arow = AB + (size_t)sdst[r] * (2 * H) + hf * 32;
    const float* Brow = AB + (size_t)ssrc[r] * (2 * H) + H + hf * 32;

    const int wm = wid >> 1;        // 0..3  -> 32-row band
    const int wn = wid & 1;         // 0..1  -> BN/2-col band
    const int m0 = wm * 32;
    const int n0 = wn * (BN / 2);

    float acc[2][NA][4];
#pragma unroll
    for (int ma = 0; ma < 2; ma++)
#pragma unroll
        for (int na = 0; na < NA; na++)
#pragma unroll
            for (int q = 0; q < 4; q++) acc[ma][na][q] = 0.f;

    const char* WhB = sm + OWH;
    const char* WlB = sm + OWL;
    char* AhB = sm + OAH;
    char* AlB = sm + OAL;

    for (int c = 0; c < NCH; c++) {
        // ---- fill A hi/lo for this K chunk ----
        {
            const float4* Ap = (const float4*)(Arow + c * 64);
            const float4* Bp = (const float4*)(Brow + c * 64);
            float v[32];
#pragma unroll
            for (int q = 0; q < 8; q++) {
                float4 a = Ap[q], b = Bp[q];
                v[q * 4 + 0] = fmaxf(a.x + b.x, 0.f);
                v[q * 4 + 1] = fmaxf(a.y + b.y, 0.f);
                v[q * 4 + 2] = fmaxf(a.z + b.z, 0.f);
                v[q * 4 + 3] = fmaxf(a.w + b.w, 0.f);
            }
            char* ah = AhB + r * (AP * 2) + hf * 64;
            char* al = AlB + r * (AP * 2) + hf * 64;
#pragma unroll
            for (int q8 = 0; q8 < 4; q8++) {
                uint32_t uh[4], ul[4];
#pragma unroll
                for (int p = 0; p < 4; p++) {
                    float v0 = v[q8 * 8 + p * 2], v1 = v[q8 * 8 + p * 2 + 1];
                    __nv_bfloat16 h0 = __float2bfloat16(v0), h1 = __float2bfloat16(v1);
                    __nv_bfloat16 l0 = __float2bfloat16(v0 - __bfloat162float(h0));
                    __nv_bfloat16 l1 = __float2bfloat16(v1 - __bfloat162float(h1));
                    uh[p] = ((uint32_t)__bfloat16_as_ushort(h1) << 16) | __bfloat16_as_ushort(h0);
                    ul[p] = ((uint32_t)__bfloat16_as_ushort(l1) << 16) | __bfloat16_as_ushort(l0);
                }
                *(uint4*)(ah + q8 * 16) = make_uint4(uh[0], uh[1], uh[2], uh[3]);
                *(uint4*)(al + q8 * 16) = make_uint4(ul[0], ul[1], ul[2], ul[3]);
            }
        }
        __syncthreads();

        // ---- mma over this chunk ----
#pragma unroll
        for (int kq = 0; kq < 4; kq++) {
            const int kl = kq * 16 + 2 * tig;          // A col (halves, chunk-local)
            const int kg = c * 64 + kl;                // W col (halves, global K)
            uint32_t ah[2][4], al[2][4];
#pragma unroll
            for (int ma = 0; ma < 2; ma++) {
                const int row = m0 + ma * 16 + g;
                const char* pa = AhB + row * (AP * 2) + kl * 2;
                const char* pl = AlB + row * (AP * 2) + kl * 2;
                ah[ma][0] = *(const uint32_t*)(pa);
                ah[ma][1] = *(const uint32_t*)(pa + 8 * (AP * 2));
                ah[ma][2] = *(const uint32_t*)(pa + 16);
                ah[ma][3] = *(const uint32_t*)(pa + 8 * (AP * 2) + 16);
                al[ma][0] = *(const uint32_t*)(pl);
                al[ma][1] = *(const uint32_t*)(pl + 8 * (AP * 2));
                al[ma][2] = *(const uint32_t*)(pl + 16);
                al[ma][3] = *(const uint32_t*)(pl + 8 * (AP * 2) + 16);
            }
#pragma unroll
            for (int na = 0; na < NA; na++) {
                const int n = n0 + na * 8 + g;
                const char* pwh = WhB + n * (KP * 2) + kg * 2;
                const char* pwl = WlB + n * (KP * 2) + kg * 2;
                uint32_t bh0 = *(const uint32_t*)(pwh);
                uint32_t bh1 = *(const uint32_t*)(pwh + 16);
                uint32_t bl0 = *(const uint32_t*)(pwl);
                uint32_t bl1 = *(const uint32_t*)(pwl + 16);
                mma_bf16(acc[0][na], ah[0], bh0, bh1);
                mma_bf16(acc[1][na], ah[1], bh0, bh1);
                mma_bf16(acc[0][na], al[0], bh0, bh1);
                mma_bf16(acc[1][na], al[1], bh0, bh1);
                mma_bf16(acc[0][na], ah[0], bl0, bl1);
                mma_bf16(acc[1][na], ah[1], bl0, bl1);
            }
        }
        __syncthreads();
    }

    // ---- epilogue: bias + ordered-uint atomicMax segment-max ----
#pragma unroll
    for (int ma = 0; ma < 2; ma++) {
#pragma unroll
        for (int rr = 0; rr < 2; rr++) {
            const int rloc = m0 + ma * 16 + g + rr * 8;
            if (e0 + rloc >= E) continue;
            const int d = sdst[rloc];
            unsigned* arow = agg + (size_t)d * COUT + bn;
#pragma unroll
            for (int na = 0; na < NA; na++) {
                const int j = n0 + na * 8 + 2 * tig;
                float v0 = acc[ma][na][rr * 2 + 0] + bias[bn + j];
                float v1 = acc[ma][na][rr * 2 + 1] + bias[bn + j + 1];
                unsigned k0 = f2ord(v0);
                if (k0 > arow[j]) atomicMax(arow + j, k0);
                unsigned k1 = f2ord(v1);
                if (k1 > arow[j + 1]) atomicMax(arow + j + 1, k1);
            }
        }
    }
}

// ---- decode agg -> float -----------------------------------------------------
__global__ void decode_kernel(const unsigned* __restrict__ agg,
                              float* __restrict__ dsth, int total, int C, int ldc) {
    int i = blockIdx.x * blockDim.x + threadIdx.x;
    if (i >= total) return;
    int n = i / C, c = i % C;
    unsigned u = agg[i];
    dsth[(size_t)n * ldc + c] = (u == 0u) ? 0.f : ord2f(u);
}
__global__ void clear_kernel(unsigned* __restrict__ p, int n) {
    int i = blockIdx.x * blockDim.x + threadIdx.x;
    if (i < n) p[i] = 0u;
}

// ---- final 256 -> 4 linear ----------------------------------------------------
__global__ void mlp3_kernel(const float* __restrict__ A, const float* __restrict__ W,
                            const float* __restrict__ b, float* __restrict__ out, int M) {
    int gw = (blockIdx.x * blockDim.x + threadIdx.x) >> 5;
    int lane = threadIdx.x & 31;
    if (gw >= M) return;
    const float* a = A + (size_t)gw * 256;
    float acc0 = 0.f, acc1 = 0.f, acc2 = 0.f, acc3 = 0.f;
    for (int k = lane; k < 256; k += 32) {
        float av = a[k];
        const float* wr = W + k * 4;
        acc0 = fmaf(av, wr[0], acc0);
        acc1 = fmaf(av, wr[1], acc1);
        acc2 = fmaf(av, wr[2], acc2);
        acc3 = fmaf(av, wr[3], acc3);
    }
#pragma unroll
    for (int off = 16; off > 0; off >>= 1) {
        acc0 += __shfl_down_sync(0xffffffffu, acc0, off);
        acc1 += __shfl_down_sync(0xffffffffu, acc1, off);
        acc2 += __shfl_down_sync(0xffffffffu, acc2, off);
        acc3 += __shfl_down_sync(0xffffffffu, acc3, off);
    }
    if (lane == 0) {
        out[gw * 4 + 0] = acc0 + b[0];
        out[gw * 4 + 1] = acc1 + b[1];
        out[gw * 4 + 2] = acc2 + b[2];
        out[gw * 4 + 3] = acc3 + b[3];
    }
}

// ---------------------------------------------------------------------------
extern "C" void kernel_launch(void* const* d_in, const int* in_sizes, int n_in,
                              void* d_out, int out_size) {
    const float* x   = (const float*)d_in[0];
    const void*  ei  = d_in[1];
    const float* w1a = (const float*)d_in[3];
    const float* b1a = (const float*)d_in[4];
    const float* w1b = (const float*)d_in[5];
    const float* b1b = (const float*)d_in[6];
    const float* w2a = (const float*)d_in[7];
    const float* b2a = (const float*)d_in[8];
    const float* w2b = (const float*)d_in[9];
    const float* b2b = (const float*)d_in[10];
    const float* w3a = (const float*)d_in[11];
    const float* b3a = (const float*)d_in[12];
    const float* w3b = (const float*)d_in[13];
    const float* b3b = (const float*)d_in[14];
    const float* wm1 = (const float*)d_in[15];
    const float* bm1 = (const float*)d_in[16];
    const float* wm2 = (const float*)d_in[17];
    const float* bm2 = (const float*)d_in[18];
    const float* wm3 = (const float*)d_in[19];
    const float* bm3 = (const float*)d_in[20];

    const int Nn = in_sizes[0] / 3;
    const int E  = in_sizes[1] / 2;
    float* out = (float*)d_out;

    float *AB, *hcat, *m1, *m2, *wc1, *wc2, *wc3, *bc1, *bc2, *bc3;
    unsigned* agg;
    uint4 *wh1, *wl1, *wh2, *wl2, *wh3, *wl3;
    cudaGetSymbolAddress((void**)&AB,   g_AB4);
    cudaGetSymbolAddress((void**)&agg,  g_agg);
    cudaGetSymbolAddress((void**)&hcat, g_hcat4);
    cudaGetSymbolAddress((void**)&m1,   g_m14);
    cudaGetSymbolAddress((void**)&m2,   g_m24);
    cudaGetSymbolAddress((void**)&wc1,  g_wc1);
    cudaGetSymbolAddress((void**)&wc2,  g_wc2);
    cudaGetSymbolAddress((void**)&wc3,  g_wc3);
    cudaGetSymbolAddress((void**)&bc1,  g_bc1);
    cudaGetSymbolAddress((void**)&bc2,  g_bc2);
    cudaGetSymbolAddress((void**)&bc3,  g_bc3);
    cudaGetSymbolAddress((void**)&wh1,  g_wh1);
    cudaGetSymbolAddress((void**)&wl1,  g_wl1);
    cudaGetSymbolAddress((void**)&wh2,  g_wh2);
    cudaGetSymbolAddress((void**)&wl2,  g_wl2);
    cudaGetSymbolAddress((void**)&wh3,  g_wh3);
    cudaGetSymbolAddress((void**)&wl3,  g_wl3);

    // dynamic smem: 1024 idx + 2*W(BN*(H+8)*2) + 2*A(128*72*2)
    const int SM1 = 1024 + 2 * (64  * 72  * 2) + 2 * 18432;  //  56320
    const int SM2 = 1024 + 2 * (128 * 136 * 2) + 2 * 18432;  // 107520
    const int SM3 = 1024 + 2 * (128 * 264 * 2) + 2 * 18432;  // 173056
    cudaFuncSetAttribute(edge_mma_kernel<64, 64>,   cudaFuncAttributeMaxDynamicSharedMemorySize, SM1);
    cudaFuncSetAttribute(edge_mma_kernel<128, 128>, cudaFuncAttributeMaxDynamicSharedMemorySize, SM2);
    cudaFuncSetAttribute(edge_mma_kernel<256, 128>, cudaFuncAttributeMaxDynamicSharedMemorySize, SM3);

    const int TB = 256;
    dim3 blk(TB);

    detect_idx_kernel<<<1, 32>>>((const unsigned*)ei, E);
    convert_idx_kernel<<<(E + TB - 1) / TB, blk>>>(ei, E);

    prep_kernel<<<1, blk>>>(w1a, b1a, wc1, bc1, 3, 64);
    prep_kernel<<<64, blk>>>(w2a, b2a, wc2, bc2, 64, 128);
    prep_kernel<<<256, blk>>>(w3a, b3a, wc3, bc3, 128, 256);
    prep_wb_kernel<<<(64 * 64 + TB - 1) / TB, blk>>>(w1b, wh1, wl1, 64, 64, 64);
    prep_wb_kernel<<<(128 * 128 + TB - 1) / TB, blk>>>(w2b, wh2, wl2, 128, 128, 128);
    prep_wb_kernel<<<(256 * 256 + TB - 1) / TB, blk>>>(w3b, wh3, wl3, 256, 256, 128);

    const int gx  = (Nn + 127) / 128;
    const int egx = (E + 127) / 128;

    // ---- EdgeConv 1: 3 -> 64 ----
    node1_kernel<<<(Nn * 128 + TB - 1) / TB, blk>>>(x, wc1, bc1, AB, Nn);
    clear_kernel<<<(Nn * 64 + TB - 1) / TB, blk>>>(agg, Nn * 64);
    edge_mma_kernel<64, 64><<<dim3(egx, 1), blk, SM1>>>(AB, wh1, wl1, b1b, agg, E, 64);
    decode_kernel<<<(Nn * 64 + TB - 1) / TB, blk>>>(agg, hcat + 0, Nn * 64, 64, 448);

    // ---- EdgeConv 2: 64 -> 128 ----
    sgemm_bias_kernel<false><<<dim3(gx, 2), blk>>>(hcat, 448, wc2, 256, bc2, AB, 256, Nn, 256, 64);
    clear_kernel<<<(Nn * 128 + TB - 1) / TB, blk>>>(agg, Nn * 128);
    edge_mma_kernel<128, 128><<<dim3(egx, 1), blk, SM2>>>(AB, wh2, wl2, b2b, agg, E, 128);
    decode_kernel<<<(Nn * 128 + TB - 1) / TB, blk>>>(agg, hcat + 64, Nn * 128, 128, 448);

    // ---- EdgeConv 3: 128 -> 256 ----
    sgemm_bias_kernel<false><<<dim3(gx, 4), blk>>>(hcat + 64, 448, wc3, 512, bc3, AB, 512, Nn, 512, 128);
    clear_kernel<<<(Nn * 256 + TB - 1) / TB, blk>>>(agg, Nn * 256);
    edge_mma_kernel<256, 128><<<dim3(egx, 2), blk, SM3>>>(AB, wh3, wl3, b3b, agg, E, 256);
    decode_kernel<<<(Nn * 256 + TB - 1) / TB, blk>>>(agg, hcat + 192, Nn * 256, 256, 448);

    // ---- MLP head ----
    sgemm_bias_kernel<true><<<dim3(gx, 4), blk>>>(hcat, 448, wm1, 512, bm1, m1, 512, Nn, 512, 448);
    sgemm_bias_kernel<true><<<dim3(gx, 2), blk>>>(m1, 512, wm2, 256, bm2, m2, 256, Nn, 256, 512);
    mlp3_kernel<<<(Nn * 32 + TB - 1) / TB, blk>>>(m2, wm3, bm3, out, Nn);
}

// round 4
// speedup vs baseline: 1.1946x; 1.1946x over previous
#include <cuda_runtime.h>
#include <cuda_bf16.h>
#include <cstdint>

// ---------------------------------------------------------------------------
// DGCNN segmentation, fp32 with packed fma.rn.f32x2 (FFMA2) inner loops.
//
// EdgeConv decomposition:  m = relu([x_i, x_j - x_i] @ W1 + b1) @ W2 + b2
//   [x_i, x_j-x_i] @ W1 = x_i @ (W1_top - W1_bot) + x_j @ W1_bot
// => per-node precompute AB = [A | B],  A = x@(Wt-Wb)+b1,  B = x@Wb
// => per-edge hidden h = relu(A[dst] + B[src]); m = h @ W2 + b2
// => segment max via ordered-uint atomicMax into agg, decoded into hcat.
// ---------------------------------------------------------------------------

#define NMAX 30016
#define EMAX 480256

__device__ float    g_AB[NMAX * 512];
__device__ unsigned g_agg[NMAX * 256];
__device__ float    g_hcat[NMAX * 448];
__device__ float    g_m1[NMAX * 512];
__device__ float    g_m2[NMAX * 256];
__device__ float    g_wc1[3 * 128];
__device__ float    g_wc2[64 * 256];
__device__ float    g_wc3[128 * 512];
__device__ float    g_bc1[128];
__device__ float    g_bc2[256];
__device__ float    g_bc3[512];
__device__ int      g_src[EMAX];
__device__ int      g_dst[EMAX];
__device__ int      g_is64;

// ---- packed f32x2 helpers ---------------------------------------------------
__device__ __forceinline__ unsigned long long bcast2(float a) {
    unsigned long long d;
    asm("mov.b64 %0, {%1, %1};" : "=l"(d) : "r"(__float_as_uint(a)));
    return d;
}
__device__ __forceinline__ void fma2(unsigned long long& d, unsigned long long a,
                                     unsigned long long b) {
    asm("fma.rn.f32x2 %0, %1, %2, %0;" : "+l"(d) : "l"(a), "l"(b));
}
__device__ __forceinline__ void unpack2(unsigned long long v, float& lo, float& hi) {
    asm("mov.b64 {%0, %1}, %2;" : "=f"(lo), "=f"(hi) : "l"(v));
}

// ---- ordered-uint encoding for float max ------------------------------------
__device__ __forceinline__ unsigned f2ord(float f) {
    int i = __float_as_int(f);
    return (i >= 0) ? ((unsigned)i | 0x80000000u) : ~(unsigned)i;
}
__device__ __forceinline__ float ord2f(unsigned u) {
    int i = (u & 0x80000000u) ? (int)(u & 0x7fffffffu) : (int)(~u);
    return __int_as_float(i);
}

// ---- edge_index dtype normalization -----------------------------------------
__global__ void detect_idx_kernel(const unsigned* __restrict__ p, int E) {
    if (threadIdx.x == 0 && blockIdx.x == 0) {
        int n = (E < 256) ? E : 256;
        int is64 = 1;
        for (int i = 0; i < n; i++)
            if (p[2 * i + 1] != 0u) { is64 = 0; break; }
        g_is64 = is64;
    }
}
__global__ void convert_idx_kernel(const void* __restrict__ raw, int E) {
    int i = blockIdx.x * blockDim.x + threadIdx.x;
    if (i >= E) return;
    if (g_is64) {
        const long long* p = (const long long*)raw;
        g_src[i] = (int)p[i];
        g_dst[i] = (int)p[E + i];
    } else {
        const int* p = (const int*)raw;
        g_src[i] = p[i];
        g_dst[i] = p[E + i];
    }
}

// ---- weight prep: wc = [Wtop - Wbot | Wbot], bc = [b | 0] --------------------
__global__ void prep_kernel(const float* __restrict__ w, const float* __restrict__ b,
                            float* __restrict__ wc, float* __restrict__ bc,
                            int C, int H) {
    int stride = gridDim.x * blockDim.x;
    int i0 = blockIdx.x * blockDim.x + threadIdx.x;
    for (int t = i0; t < C * H; t += stride) {
        int k = t / H, j = t % H;
        float wd = w[(k + C) * H + j];
        wc[k * 2 * H + j]     = w[k * H + j] - wd;
        wc[k * 2 * H + H + j] = wd;
    }
    for (int t = i0; t < H; t += stride) {
        bc[t]     = b[t];
        bc[H + t] = 0.f;
    }
}

// ---- layer-1 node precompute: K=3 --------------------------------------------
__global__ void node1_kernel(const float* __restrict__ x,
                             const float* __restrict__ wc,
                             const float* __restrict__ bc,
                             float* __restrict__ AB, int M) {
    int idx = blockIdx.x * blockDim.x + threadIdx.x;
    if (idx >= M * 128) return;
    int n = idx >> 7, j = idx & 127;
    float x0 = x[n * 3 + 0], x1 = x[n * 3 + 1], x2 = x[n * 3 + 2];
    AB[idx] = fmaf(x0, wc[j], fmaf(x1, wc[128 + j], fmaf(x2, wc[256 + j], bc[j])));
}

// ---- tiled SGEMM with FFMA2: C = act(A[M,K](lda) @ W[K,N](ldw) + bias) -------
template <bool RELU>
__global__ void __launch_bounds__(256, 2)
sgemm_bias_kernel(const float* __restrict__ A, int lda,
                  const float* __restrict__ W, int ldw,
                  const float* __restrict__ bias,
                  float* __restrict__ C, int ldc,
                  int M, int N, int K) {
    constexpr int BM = 128, BN = 128, BK = 16;
    __shared__ float As[BK][BM + 4];
    __shared__ float Ws[BK][BN];
    const int tid = threadIdx.x;
    const int bm = blockIdx.x * BM;
    const int bn = blockIdx.y * BN;
    const int rowb = (tid / 16) * 8;
    const int colb = (tid % 16) * 8;
    const int a_m = tid >> 2;
    const int a_k = (tid & 3) * 4;
    const int w_r = tid >> 4;
    const int w_c = (tid & 15) * 8;

    unsigned long long acc2[8][4];
#pragma unroll
    for (int i = 0; i < 8; i++)
#pragma unroll
        for (int q = 0; q < 4; q++) acc2[i][q] = 0ULL;

    for (int k0 = 0; k0 < K; k0 += BK) {
#pragma unroll
        for (int p = 0; p < 2; p++) {
            int m = a_m + p * 64;
            float4 v = make_float4(0.f, 0.f, 0.f, 0.f);
            if (bm + m < M)
                v = *reinterpret_cast<const float4*>(A + (size_t)(bm + m) * lda + k0 + a_k);
            As[a_k + 0][m] = v.x; As[a_k + 1][m] = v.y;
            As[a_k + 2][m] = v.z; As[a_k + 3][m] = v.w;
        }
#pragma unroll
        for (int q = 0; q < 2; q++)
            *reinterpret_cast<float4*>(&Ws[w_r][w_c + q * 4]) =
                *reinterpret_cast<const float4*>(W + (size_t)(k0 + w_r) * ldw + bn + w_c + q * 4);
        __syncthreads();
#pragma unroll
        for (int kk = 0; kk < BK; kk++) {
            unsigned long long wp[4];
#pragma unroll
            for (int q = 0; q < 4; q++)
                wp[q] = *reinterpret_cast<const unsigned long long*>(&Ws[kk][colb + 2 * q]);
            float af[8];
#pragma unroll
            for (int h = 0; h < 4; h++) {
                float2 a2 = *reinterpret_cast<const float2*>(&As[kk][rowb + 2 * h]);
                af[2 * h] = a2.x; af[2 * h + 1] = a2.y;
            }
#pragma unroll
            for (int i = 0; i < 8; i++) {
                unsigned long long aa = bcast2(af[i]);
#pragma unroll
                for (int q = 0; q < 4; q++) fma2(acc2[i][q], aa, wp[q]);
            }
        }
        __syncthreads();
    }

#pragma unroll
    for (int i = 0; i < 8; i++) {
        int m = bm + rowb + i;
        if (m >= M) break;
#pragma unroll
        for (int q = 0; q < 4; q++) {
            float lo, hi;
            unpack2(acc2[i][q], lo, hi);
            float v0 = lo + bias[bn + colb + 2 * q];
            float v1 = hi + bias[bn + colb + 2 * q + 1];
            if (RELU) { v0 = fmaxf(v0, 0.f); v1 = fmaxf(v1, 0.f); }
            C[(size_t)m * ldc + bn + colb + 2 * q]     = v0;
            C[(size_t)m * ldc + bn + colb + 2 * q + 1] = v1;
        }
    }
}

// ---- fused edge kernel with FFMA2 --------------------------------------------
template <int H, int COUT, int BN>
__global__ void __launch_bounds__(256, 2)
edge_conv_kernel(const float* __restrict__ AB,
                 const float* __restrict__ W2,   // [H, COUT] row-major
                 const float* __restrict__ b2,
                 unsigned* __restrict__ agg,     // [N, COUT]
                 int E) {
    constexpr int BM = 128, BK = 16;
    constexpr int CN = BN / 16;
    constexpr int CQ = CN / 2;
    __shared__ float Hs[BK][BM + 4];
    __shared__ float Ws[BK][BN];
    __shared__ int ssrc[BM];
    __shared__ int sdst[BM];

    const int tid = threadIdx.x;
    const int e0 = blockIdx.x * BM;
    const int bn = blockIdx.y * BN;

    if (tid < BM) {
        int e = e0 + tid;
        ssrc[tid] = (e < E) ? g_src[e] : 0;
    } else {
        int e = e0 + tid - BM;
        sdst[tid - BM] = (e < E) ? g_dst[e] : 0;
    }
    __syncthreads();

    const int rowb = (tid / 16) * 8;
    const int colb = (tid % 16) * CN;
    const int g_m = tid >> 1;
    const int g_h = (tid & 1) * 8;
    const int w_r = tid >> 4;
    const int w_c = (tid & 15) * CN;

    unsigned long long acc2[8][CQ];
#pragma unroll
    for (int i = 0; i < 8; i++)
#pragma unroll
        for (int q = 0; q < CQ; q++) acc2[i][q] = 0ULL;

    const float* Abase = AB + (size_t)sdst[g_m] * (2 * H) + g_h;
    const float* Bbase = AB + (size_t)ssrc[g_m] * (2 * H) + H + g_h;

    for (int k0 = 0; k0 < H; k0 += BK) {
        float4 a0 = *reinterpret_cast<const float4*>(Abase + k0);
        float4 a1 = *reinterpret_cast<const float4*>(Abase + k0 + 4);
        float4 c0 = *reinterpret_cast<const float4*>(Bbase + k0);
        float4 c1 = *reinterpret_cast<const float4*>(Bbase + k0 + 4);
        Hs[g_h + 0][g_m] = fmaxf(a0.x + c0.x, 0.f);
        Hs[g_h + 1][g_m] = fmaxf(a0.y + c0.y, 0.f);
        Hs[g_h + 2][g_m] = fmaxf(a0.z + c0.z, 0.f);
        Hs[g_h + 3][g_m] = fmaxf(a0.w + c0.w, 0.f);
        Hs[g_h + 4][g_m] = fmaxf(a1.x + c1.x, 0.f);
        Hs[g_h + 5][g_m] = fmaxf(a1.y + c1.y, 0.f);
        Hs[g_h + 6][g_m] = fmaxf(a1.z + c1.z, 0.f);
        Hs[g_h + 7][g_m] = fmaxf(a1.w + c1.w, 0.f);
#pragma unroll
        for (int q = 0; q < CN / 4; q++) {
            *reinterpret_cast<float4*>(&Ws[w_r][w_c + q * 4]) =
                *reinterpret_cast<const float4*>(W2 + (size_t)(k0 + w_r) * COUT + bn + w_c + q * 4);
        }
        __syncthreads();
#pragma unroll
        for (int kk = 0; kk < BK; kk++) {
            unsigned long long wp[CQ];
#pragma unroll
            for (int q = 0; q < CQ; q++)
                wp[q] = *reinterpret_cast<const unsigned long long*>(&Ws[kk][colb + 2 * q]);
            float af[8];
#pragma unroll
            for (int h = 0; h < 4; h++) {
                float2 a2 = *reinterpret_cast<const float2*>(&Hs[kk][rowb + 2 * h]);
                af[2 * h] = a2.x; af[2 * h + 1] = a2.y;
            }
#pragma unroll
            for (int i = 0; i < 8; i++) {
                unsigned long long aa = bcast2(af[i]);
#pragma unroll
                for (int q = 0; q < CQ; q++) fma2(acc2[i][q], aa, wp[q]);
            }
        }
        __syncthreads();
    }

#pragma unroll
    for (int i = 0; i < 8; i++) {
        int e = rowb + i;
        if (e0 + e >= E) break;
        unsigned* arow = agg + (size_t)sdst[e] * COUT + bn + colb;
#pragma unroll
        for (int q = 0; q < CQ; q++) {
            float lo, hi;
            unpack2(acc2[i][q], lo, hi);
            float v0 = lo + b2[bn + colb + 2 * q];
            float v1 = hi + b2[bn + colb + 2 * q + 1];
            unsigned k0 = f2ord(v0);
            if (k0 > arow[2 * q]) atomicMax(arow + 2 * q, k0);
            unsigned k1 = f2ord(v1);
            if (k1 > arow[2 * q + 1]) atomicMax(arow + 2 * q + 1, k1);
        }
    }
}

// ---- decode agg -> float, empty segments (sentinel 0u) -> 0 ------------------
__global__ void decode_kernel(const unsigned* __restrict__ agg,
                              float* __restrict__ dsth, int total, int C, int ldc) {
    int i = blockIdx.x * blockDim.x + threadIdx.x;
    if (i >= total) return;
    int n = i / C, c = i % C;
    unsigned u = agg[i];
    dsth[(size_t)n * ldc + c] = (u == 0u) ? 0.f : ord2f(u);
}

__global__ void clear_kernel(unsigned* __restrict__ p, int n) {
    int i = blockIdx.x * blockDim.x + threadIdx.x;
    if (i < n) p[i] = 0u;
}

// ---- final 256 -> 4 linear: one warp per node ---------------------------------
__global__ void mlp3_kernel(const float* __restrict__ A, const float* __restrict__ W,
                            const float* __restrict__ b, float* __restrict__ out, int M) {
    int gw = (blockIdx.x * blockDim.x + threadIdx.x) >> 5;
    int lane = threadIdx.x & 31;
    if (gw >= M) return;
    const float* a = A + (size_t)gw * 256;
    float acc0 = 0.f, acc1 = 0.f, acc2 = 0.f, acc3 = 0.f;
    for (int k = lane; k < 256; k += 32) {
        float av = a[k];
        const float* wr = W + k * 4;
        acc0 = fmaf(av, wr[0], acc0);
        acc1 = fmaf(av, wr[1], acc1);
        acc2 = fmaf(av, wr[2], acc2);
        acc3 = fmaf(av, wr[3], acc3);
    }
#pragma unroll
    for (int off = 16; off > 0; off >>= 1) {
        acc0 += __shfl_down_sync(0xffffffffu, acc0, off);
        acc1 += __shfl_down_sync(0xffffffffu, acc1, off);
        acc2 += __shfl_down_sync(0xffffffffu, acc2, off);
        acc3 += __shfl_down_sync(0xffffffffu, acc3, off);
    }
    if (lane == 0) {
        out[gw * 4 + 0] = acc0 + b[0];
        out[gw * 4 + 1] = acc1 + b[1];
        out[gw * 4 + 2] = acc2 + b[2];
        out[gw * 4 + 3] = acc3 + b[3];
    }
}

// ---------------------------------------------------------------------------
extern "C" void kernel_launch(void* const* d_in, const int* in_sizes, int n_in,
                              void* d_out, int out_size) {
    const float* x   = (const float*)d_in[0];
    const void*  ei  = d_in[1];
    const float* w1a = (const float*)d_in[3];
    const float* b1a = (const float*)d_in[4];
    const float* w1b = (const float*)d_in[5];
    const float* b1b = (const float*)d_in[6];
    const float* w2a = (const float*)d_in[7];
    const float* b2a = (const float*)d_in[8];
    const float* w2b = (const float*)d_in[9];
    const float* b2b = (const float*)d_in[10];
    const float* w3a = (const float*)d_in[11];
    const float* b3a = (const float*)d_in[12];
    const float* w3b = (const float*)d_in[13];
    const float* b3b = (const float*)d_in[14];
    const float* wm1 = (const float*)d_in[15];
    const float* bm1 = (const float*)d_in[16];
    const float* wm2 = (const float*)d_in[17];
    const float* bm2 = (const float*)d_in[18];
    const float* wm3 = (const float*)d_in[19];
    const float* bm3 = (const float*)d_in[20];

    const int Nn = in_sizes[0] / 3;
    const int E  = in_sizes[1] / 2;
    float* out = (float*)d_out;

    float *AB, *hcat, *m1, *m2, *wc1, *wc2, *wc3, *bc1, *bc2, *bc3;
    unsigned* agg;
    cudaGetSymbolAddress((void**)&AB,   g_AB);
    cudaGetSymbolAddress((void**)&agg,  g_agg);
    cudaGetSymbolAddress((void**)&hcat, g_hcat);
    cudaGetSymbolAddress((void**)&m1,   g_m1);
    cudaGetSymbolAddress((void**)&m2,   g_m2);
    cudaGetSymbolAddress((void**)&wc1,  g_wc1);
    cudaGetSymbolAddress((void**)&wc2,  g_wc2);
    cudaGetSymbolAddress((void**)&wc3,  g_wc3);
    cudaGetSymbolAddress((void**)&bc1,  g_bc1);
    cudaGetSymbolAddress((void**)&bc2,  g_bc2);
    cudaGetSymbolAddress((void**)&bc3,  g_bc3);

    const int TB = 256;
    dim3 blk(TB);

    detect_idx_kernel<<<1, 32>>>((const unsigned*)ei, E);
    convert_idx_kernel<<<(E + TB - 1) / TB, blk>>>(ei, E);

    prep_kernel<<<1, blk>>>(w1a, b1a, wc1, bc1, 3, 64);
    prep_kernel<<<64, blk>>>(w2a, b2a, wc2, bc2, 64, 128);
    prep_kernel<<<256, blk>>>(w3a, b3a, wc3, bc3, 128, 256);

    const int gx = (Nn + 127) / 128;
    const int egx = (E + 127) / 128;

    // ---- EdgeConv 1: 3 -> 64 ----
    node1_kernel<<<(Nn * 128 + TB - 1) / TB, blk>>>(x, wc1, bc1, AB, Nn);
    clear_kernel<<<(Nn * 64 + TB - 1) / TB, blk>>>(agg, Nn * 64);
    edge_conv_kernel<64, 64, 64><<<dim3(egx, 1), blk>>>(AB, w1b, b1b, agg, E);
    decode_kernel<<<(Nn * 64 + TB - 1) / TB, blk>>>(agg, hcat + 0, Nn * 64, 64, 448);

    // ---- EdgeConv 2: 64 -> 128 ----
    sgemm_bias_kernel<false><<<dim3(gx, 2), blk>>>(hcat, 448, wc2, 256, bc2, AB, 256, Nn, 256, 64);
    clear_kernel<<<(Nn * 128 + TB - 1) / TB, blk>>>(agg, Nn * 128);
    edge_conv_kernel<128, 128, 128><<<dim3(egx, 1), blk>>>(AB, w2b, b2b, agg, E);
    decode_kernel<<<(Nn * 128 + TB - 1) / TB, blk>>>(agg, hcat + 64, Nn * 128, 128, 448);

    // ---- EdgeConv 3: 128 -> 256 ----
    sgemm_bias_kernel<false><<<dim3(gx, 4), blk>>>(hcat + 64, 448, wc3, 512, bc3, AB, 512, Nn, 512, 128);
    clear_kernel<<<(Nn * 256 + TB - 1) / TB, blk>>>(agg, Nn * 256);
    edge_conv_kernel<256, 256, 128><<<dim3(egx, 2), blk>>>(AB, w3b, b3b, agg, E);
    decode_kernel<<<(Nn * 256 + TB - 1) / TB, blk>>>(agg, hcat + 192, Nn * 256, 256, 448);

    // ---- MLP head ----
    sgemm_bias_kernel<true><<<dim3(gx, 4), blk>>>(hcat, 448, wm1, 512, bm1, m1, 512, Nn, 512, 448);
    sgemm_bias_kernel<true><<<dim3(gx, 2), blk>>>(m1, 512, wm2, 256, bm2, m2, 256, Nn, 256, 512);
    mlp3_kernel<<<(Nn * 32 + TB - 1) / TB, blk>>>(m2, wm3, bm3, out, Nn);
}

// round 5
// speedup vs baseline: 1.3164x; 1.1019x over previous
#include <cuda_runtime.h>
#include <cuda_bf16.h>
#include <cstdint>

// ---------------------------------------------------------------------------
// DGCNN segmentation. Edge GEMMs: mma.sync bf16x3 split precision, W streamed
// per 64-wide K chunk (occupancy 2). Node precompute + MLP head: fp32 (R1).
//
// EdgeConv:  m = relu([x_i, x_j-x_i] @ W1 + b1) @ W2 + b2
//   per-node AB = [A | B];  per-edge h = relu(A[dst]+B[src]);  m = h@W2+b2;
//   segment-max(dst) via ordered-uint atomicMax.
// ---------------------------------------------------------------------------

#define NMAX 30016
#define EMAX 480256

__device__ float    g_AB[NMAX * 512];
__device__ unsigned g_agg[NMAX * 256];
__device__ float    g_hcat[NMAX * 448];
__device__ float    g_m1[NMAX * 512];
__device__ float    g_m2[NMAX * 256];
__device__ float    g_wc2[64 * 256];
__device__ float    g_wc3[128 * 512];
__device__ float    g_bc2[256];
__device__ float    g_bc3[512];
// W^T bf16 hi/lo, chunked layout: [(tile*NCH + chunk)*BN + n][72] halves
__device__ uint4    g_wh1[64 * 72 / 8],       g_wl1[64 * 72 / 8];
__device__ uint4    g_wh2[2 * 128 * 72 / 8],  g_wl2[2 * 128 * 72 / 8];
__device__ uint4    g_wh3[8 * 128 * 72 / 8],  g_wl3[8 * 128 * 72 / 8];
__device__ int      g_src[EMAX];
__device__ int      g_dst[EMAX];

// ---- ordered-uint encoding for float max ------------------------------------
__device__ __forceinline__ unsigned f2ord(float f) {
    int i = __float_as_int(f);
    return (i >= 0) ? ((unsigned)i | 0x80000000u) : ~(unsigned)i;
}
__device__ __forceinline__ float ord2f(unsigned u) {
    int i = (u & 0x80000000u) ? (int)(u & 0x7fffffffu) : (int)(~u);
    return __int_as_float(i);
}

// ---- bf16 mma.sync m16n8k16 (fp32 accum) --------------------------------------
__device__ __forceinline__ void mma_bf16(float* d, const uint32_t* a,
                                         uint32_t b0, uint32_t b1) {
    asm volatile(
        "mma.sync.aligned.m16n8k16.row.col.f32.bf16.bf16.f32 "
        "{%0,%1,%2,%3},{%4,%5,%6,%7},{%8,%9},{%0,%1,%2,%3};"
        : "+f"(d[0]), "+f"(d[1]), "+f"(d[2]), "+f"(d[3])
        : "r"(a[0]), "r"(a[1]), "r"(a[2]), "r"(a[3]), "r"(b0), "r"(b1));
}

// ---- edge index convert with inline dtype detection ---------------------------
__global__ void convert_idx_kernel(const unsigned* __restrict__ raw, int E) {
    int n = (E < 256) ? E : 256;
    int is64 = 1;
    for (int i = 0; i < n; i++)
        if (raw[2 * i + 1] != 0u) { is64 = 0; break; }   // int64 high words are 0
    int i = blockIdx.x * blockDim.x + threadIdx.x;
    if (i >= E) return;
    if (is64) {
        const long long* p = (const long long*)raw;
        g_src[i] = (int)p[i];
        g_dst[i] = (int)p[E + i];
    } else {
        const int* p = (const int*)raw;
        g_src[i] = p[i];
        g_dst[i] = p[E + i];
    }
}

// ---- weight prep: wc = [Wtop - Wbot | Wbot], bc = [b | 0] ---------------------
__global__ void prep_kernel(const float* __restrict__ w, const float* __restrict__ b,
                            float* __restrict__ wc, float* __restrict__ bc,
                            int C, int H) {
    int stride = gridDim.x * blockDim.x;
    int i0 = blockIdx.x * blockDim.x + threadIdx.x;
    for (int t = i0; t < C * H; t += stride) {
        int k = t / H, j = t % H;
        float wd = w[(k + C) * H + j];
        wc[k * 2 * H + j]     = w[k * H + j] - wd;
        wc[k * 2 * H + H + j] = wd;
    }
    for (int t = i0; t < H; t += stride) { bc[t] = b[t]; bc[H + t] = 0.f; }
}

// ---- weight prep: W^T bf16 hi/lo chunked [(tile*NCH+c)*BN + n][72] ------------
__global__ void prep_wb_kernel(const float* __restrict__ W,  // [H, COUT] row-major
                               uint4* __restrict__ Whi, uint4* __restrict__ Wlo,
                               int H, int COUT, int BN) {
    int i = blockIdx.x * blockDim.x + threadIdx.x;
    if (i >= H * COUT) return;
    int k = i / COUT, n = i % COUT;
    float w = W[i];
    __nv_bfloat16 hb = __float2bfloat16(w);
    __nv_bfloat16 lb = __float2bfloat16(w - __bfloat162float(hb));
    int NCH = H >> 6;
    int tile = n / BN, nl = n % BN, c = k >> 6, kl = k & 63;
    size_t off = ((size_t)(tile * NCH + c) * BN + nl) * 72 + kl;   // halves
    ((unsigned short*)Whi)[off] = __bfloat16_as_ushort(hb);
    ((unsigned short*)Wlo)[off] = __bfloat16_as_ushort(lb);
}

// ---- layer-1 node precompute fused with wc1 prep + agg clear ------------------
__global__ void node1_fused_kernel(const float* __restrict__ x,
                                   const float* __restrict__ w1a,
                                   const float* __restrict__ b1a,
                                   float* __restrict__ AB,
                                   unsigned* __restrict__ agg, int M) {
    int idx = blockIdx.x * blockDim.x + threadIdx.x;
    if (idx >= M * 128) return;
    if (idx < M * 64) agg[idx] = 0u;
    int n = idx >> 7, j = idx & 127;
    float wk0, wk1, wk2, bb;
    if (j < 64) {
        wk0 = w1a[0 * 64 + j] - w1a[3 * 64 + j];
        wk1 = w1a[1 * 64 + j] - w1a[4 * 64 + j];
        wk2 = w1a[2 * 64 + j] - w1a[5 * 64 + j];
        bb  = b1a[j];
    } else {
        int jj = j - 64;
        wk0 = w1a[3 * 64 + jj];
        wk1 = w1a[4 * 64 + jj];
        wk2 = w1a[5 * 64 + jj];
        bb  = 0.f;
    }
    float x0 = x[n * 3 + 0], x1 = x[n * 3 + 1], x2 = x[n * 3 + 2];
    AB[idx] = fmaf(x0, wk0, fmaf(x1, wk1, fmaf(x2, wk2, bb)));
}

// ---- fp32 tiled SGEMM (node precompute + MLP head, proven R1) -----------------
template <bool RELU>
__global__ void __launch_bounds__(256, 2)
sgemm_bias_kernel(const float* __restrict__ A, int lda,
                  const float* __restrict__ W, int ldw,
                  const float* __restrict__ bias,
                  float* __restrict__ C, int ldc, int M, int N, int K) {
    constexpr int BM = 128, BN = 128, BK = 16;
    __shared__ float As[BK][BM + 4];
    __shared__ float Ws[BK][BN];
    const int tid = threadIdx.x;
    const int bm = blockIdx.x * BM;
    const int bn = blockIdx.y * BN;
    const int rowb = (tid / 16) * 8;
    const int colb = (tid % 16) * 8;
    const int a_m = tid >> 2;
    const int a_k = (tid & 3) * 4;
    const int w_r = tid >> 4;
    const int w_c = (tid & 15) * 8;

    float acc[8][8];
#pragma unroll
    for (int i = 0; i < 8; i++)
#pragma unroll
        for (int j = 0; j < 8; j++) acc[i][j] = 0.f;

    for (int k0 = 0; k0 < K; k0 += BK) {
#pragma unroll
        for (int p = 0; p < 2; p++) {
            int m = a_m + p * 64;
            float4 v = make_float4(0.f, 0.f, 0.f, 0.f);
            if (bm + m < M)
                v = *reinterpret_cast<const float4*>(A + (size_t)(bm + m) * lda + k0 + a_k);
            As[a_k + 0][m] = v.x; As[a_k + 1][m] = v.y;
            As[a_k + 2][m] = v.z; As[a_k + 3][m] = v.w;
        }
#pragma unroll
        for (int q = 0; q < 2; q++)
            *reinterpret_cast<float4*>(&Ws[w_r][w_c + q * 4]) =
                *reinterpret_cast<const float4*>(W + (size_t)(k0 + w_r) * ldw + bn + w_c + q * 4);
        __syncthreads();
#pragma unroll
        for (int kk = 0; kk < BK; kk++) {
            float af[8], wf[8];
#pragma unroll
            for (int i = 0; i < 8; i++) af[i] = As[kk][rowb + i];
#pragma unroll
            for (int j = 0; j < 8; j++) wf[j] = Ws[kk][colb + j];
#pragma unroll
            for (int i = 0; i < 8; i++)
#pragma unroll
                for (int j = 0; j < 8; j++) acc[i][j] = fmaf(af[i], wf[j], acc[i][j]);
        }
        __syncthreads();
    }
#pragma unroll
    for (int i = 0; i < 8; i++) {
        int m = bm + rowb + i;
        if (m >= M) break;
#pragma unroll
        for (int j = 0; j < 8; j++) {
            float v = acc[i][j] + bias[bn + colb + j];
            if (RELU) v = fmaxf(v, 0.f);
            C[(size_t)m * ldc + bn + colb + j] = v;
        }
    }
}

// ---- mma.sync edge kernel, W streamed per 64-K chunk, occ 2 -------------------
// Block: 256 thr = 8 warps (4 m x 2 n). Tile: 128 edges x BN outputs, K = H.
template <int H, int BN>
__global__ void __launch_bounds__(256, 2)
edge_mma_kernel(const float* __restrict__ AB,
                const uint4* __restrict__ Whi_g, const uint4* __restrict__ Wlo_g,
                const float* __restrict__ bias,
                unsigned* __restrict__ agg, int E, int COUT) {
    constexpr int NCH = H / 64;
    constexpr int NA  = BN / 16;            // n atoms per warp
    constexpr int WSZ = BN * 144;           // bytes per W chunk array (pitch 72 halves)
    constexpr int ASZ = 128 * 144;          // bytes per A array
    constexpr int OW  = 1024;
    constexpr int OA  = OW + 2 * WSZ;
    constexpr int WCNT = BN * 9;            // uint4 per W array per chunk

    extern __shared__ char sm[];
    int* sdst = (int*)sm;
    int* ssrc = (int*)(sm + 512);

    const int tid = threadIdx.x;
    const int wid = tid >> 5, lane = tid & 31;
    const int g = lane >> 2, tig = lane & 3;
    const int e0 = blockIdx.x * 128;
    const int bn = blockIdx.y * BN;

    if (tid < 128) { int e = e0 + tid; ssrc[tid] = (e < E) ? g_src[e] : 0; }
    else           { int e = e0 + tid - 128; sdst[tid - 128] = (e < E) ? g_dst[e] : 0; }
    __syncthreads();

    const int r  = tid >> 1;          // edge row this thread fills
    const int hf = tid & 1;           // 32-col half of the 64-chunk
    const float* Arow = AB + (size_t)sdst[r] * (2 * H) + hf * 32;
    const float* Brow = AB + (size_t)ssrc[r] * (2 * H) + H + hf * 32;

    const int wm = wid >> 1, wn = wid & 1;
    const int m0 = wm * 32, n0 = wn * (BN / 2);

    float acc[2][NA][4];
#pragma unroll
    for (int ma = 0; ma < 2; ma++)
#pragma unroll
        for (int na = 0; na < NA; na++)
#pragma unroll
            for (int q = 0; q < 4; q++) acc[ma][na][q] = 0.f;

    char* Wh = sm + OW;
    char* Wl = sm + OW + WSZ;
    char* Ah = sm + OA;
    char* Al = sm + OA + ASZ;

    for (int c = 0; c < NCH; c++) {
        if (c) __syncthreads();   // smem reuse barrier

        // ---- copy W chunk (pre-chunked, contiguous) ----
        {
            const uint4* shp = Whi_g + (size_t)(blockIdx.y * NCH + c) * WCNT;
            const uint4* slp = Wlo_g + (size_t)(blockIdx.y * NCH + c) * WCNT;
            for (int i = tid; i < WCNT; i += 256) {
                ((uint4*)Wh)[i] = shp[i];
                ((uint4*)Wl)[i] = slp[i];
            }
        }
        // ---- fill A hi/lo for this chunk ----
        {
            const float4* Ap = (const float4*)(Arow + c * 64);
            const float4* Bp = (const float4*)(Brow + c * 64);
            float v[32];
#pragma unroll
            for (int q = 0; q < 8; q++) {
                float4 a = Ap[q], b = Bp[q];
                v[q * 4 + 0] = fmaxf(a.x + b.x, 0.f);
                v[q * 4 + 1] = fmaxf(a.y + b.y, 0.f);
                v[q * 4 + 2] = fmaxf(a.z + b.z, 0.f);
                v[q * 4 + 3] = fmaxf(a.w + b.w, 0.f);
            }
            char* ah = Ah + r * 144 + hf * 64;
            char* al = Al + r * 144 + hf * 64;
#pragma unroll
            for (int q8 = 0; q8 < 4; q8++) {
                uint32_t uh[4], ul[4];
#pragma unroll
                for (int p = 0; p < 4; p++) {
                    float v0 = v[q8 * 8 + p * 2], v1 = v[q8 * 8 + p * 2 + 1];
                    __nv_bfloat16 h0 = __float2bfloat16(v0), h1 = __float2bfloat16(v1);
                    __nv_bfloat16 l0 = __float2bfloat16(v0 - __bfloat162float(h0));
                    __nv_bfloat16 l1 = __float2bfloat16(v1 - __bfloat162float(h1));
                    uh[p] = ((uint32_t)__bfloat16_as_ushort(h1) << 16) | __bfloat16_as_ushort(h0);
                    ul[p] = ((uint32_t)__bfloat16_as_ushort(l1) << 16) | __bfloat16_as_ushort(l0);
                }
                *(uint4*)(ah + q8 * 16) = make_uint4(uh[0], uh[1], uh[2], uh[3]);
                *(uint4*)(al + q8 * 16) = make_uint4(ul[0], ul[1], ul[2], ul[3]);
            }
        }
        __syncthreads();

        // ---- mma over this chunk ----
#pragma unroll
        for (int kq = 0; kq < 4; kq++) {
            const int kl = kq * 16 + 2 * tig;          // local k (halves)
            uint32_t ah[2][4], al[2][4];
#pragma unroll
            for (int ma = 0; ma < 2; ma++) {
                const int row = m0 + ma * 16 + g;
                const char* pa = Ah + row * 144 + kl * 2;
                const char* pl = Al + row * 144 + kl * 2;
                ah[ma][0] = *(const uint32_t*)(pa);
                ah[ma][1] = *(const uint32_t*)(pa + 8 * 144);
                ah[ma][2] = *(const uint32_t*)(pa + 16);
                ah[ma][3] = *(const uint32_t*)(pa + 8 * 144 + 16);
                al[ma][0] = *(const uint32_t*)(pl);
                al[ma][1] = *(const uint32_t*)(pl + 8 * 144);
                al[ma][2] = *(const uint32_t*)(pl + 16);
                al[ma][3] = *(const uint32_t*)(pl + 8 * 144 + 16);
            }
#pragma unroll
            for (int na = 0; na < NA; na++) {
                const int n = n0 + na * 8 + g;
                const char* pwh = Wh + n * 144 + kl * 2;
                const char* pwl = Wl + n * 144 + kl * 2;
                uint32_t bh0 = *(const uint32_t*)(pwh);
                uint32_t bh1 = *(const uint32_t*)(pwh + 16);
                uint32_t bl0 = *(const uint32_t*)(pwl);
                uint32_t bl1 = *(const uint32_t*)(pwl + 16);
                mma_bf16(acc[0][na], ah[0], bh0, bh1);
                mma_bf16(acc[1][na], ah[1], bh0, bh1);
                mma_bf16(acc[0][na], al[0], bh0, bh1);
                mma_bf16(acc[1][na], al[1], bh0, bh1);
                mma_bf16(acc[0][na], ah[0], bl0, bl1);
                mma_bf16(acc[1][na], ah[1], bl0, bl1);
            }
        }
    }

    // ---- epilogue: bias + ordered-uint atomicMax segment-max ----
#pragma unroll
    for (int ma = 0; ma < 2; ma++) {
#pragma unroll
        for (int rr = 0; rr < 2; rr++) {
            const int rloc = m0 + ma * 16 + g + rr * 8;
            if (e0 + rloc >= E) continue;
            const int d = sdst[rloc];
            unsigned* arow = agg + (size_t)d * COUT + bn;
#pragma unroll
            for (int na = 0; na < NA; na++) {
                const int j = n0 + na * 8 + 2 * tig;
                float v0 = acc[ma][na][rr * 2 + 0] + bias[bn + j];
                float v1 = acc[ma][na][rr * 2 + 1] + bias[bn + j + 1];
                unsigned k0 = f2ord(v0);
                if (k0 > arow[j]) atomicMax(arow + j, k0);
                unsigned k1 = f2ord(v1);
                if (k1 > arow[j + 1]) atomicMax(arow + j + 1, k1);
            }
        }
    }
}

// ---- decode agg -> float -------------------------------------------------------
__global__ void decode_kernel(const unsigned* __restrict__ agg,
                              float* __restrict__ dsth, int total, int C, int ldc) {
    int i = blockIdx.x * blockDim.x + threadIdx.x;
    if (i >= total) return;
    int n = i / C, c = i % C;
    unsigned u = agg[i];
    dsth[(size_t)n * ldc + c] = (u == 0u) ? 0.f : ord2f(u);
}
__global__ void clear_kernel(unsigned* __restrict__ p, int n) {
    int i = blockIdx.x * blockDim.x + threadIdx.x;
    if (i < n) p[i] = 0u;
}

// ---- final 256 -> 4 linear ------------------------------------------------------
__global__ void mlp3_kernel(const float* __restrict__ A, const float* __restrict__ W,
                            const float* __restrict__ b, float* __restrict__ out, int M) {
    int gw = (blockIdx.x * blockDim.x + threadIdx.x) >> 5;
    int lane = threadIdx.x & 31;
    if (gw >= M) return;
    const float* a = A + (size_t)gw * 256;
    float acc0 = 0.f, acc1 = 0.f, acc2 = 0.f, acc3 = 0.f;
    for (int k = lane; k < 256; k += 32) {
        float av = a[k];
        const float* wr = W + k * 4;
        acc0 = fmaf(av, wr[0], acc0);
        acc1 = fmaf(av, wr[1], acc1);
        acc2 = fmaf(av, wr[2], acc2);
        acc3 = fmaf(av, wr[3], acc3);
    }
#pragma unroll
    for (int off = 16; off > 0; off >>= 1) {
        acc0 += __shfl_down_sync(0xffffffffu, acc0, off);
        acc1 += __shfl_down_sync(0xffffffffu, acc1, off);
        acc2 += __shfl_down_sync(0xffffffffu, acc2, off);
        acc3 += __shfl_down_sync(0xffffffffu, acc3, off);
    }
    if (lane == 0) {
        out[gw * 4 + 0] = acc0 + b[0];
        out[gw * 4 + 1] = acc1 + b[1];
        out[gw * 4 + 2] = acc2 + b[2];
        out[gw * 4 + 3] = acc3 + b[3];
    }
}

// ---------------------------------------------------------------------------
extern "C" void kernel_launch(void* const* d_in, const int* in_sizes, int n_in,
                              void* d_out, int out_size) {
    const float* x   = (const float*)d_in[0];
    const void*  ei  = d_in[1];
    const float* w1a = (const float*)d_in[3];
    const float* b1a = (const float*)d_in[4];
    const float* w1b = (const float*)d_in[5];
    const float* b1b = (const float*)d_in[6];
    const float* w2a = (const float*)d_in[7];
    const float* b2a = (const float*)d_in[8];
    const float* w2b = (const float*)d_in[9];
    const float* b2b = (const float*)d_in[10];
    const float* w3a = (const float*)d_in[11];
    const float* b3a = (const float*)d_in[12];
    const float* w3b = (const float*)d_in[13];
    const float* b3b = (const float*)d_in[14];
    const float* wm1 = (const float*)d_in[15];
    const float* bm1 = (const float*)d_in[16];
    const float* wm2 = (const float*)d_in[17];
    const float* bm2 = (const float*)d_in[18];
    const float* wm3 = (const float*)d_in[19];
    const float* bm3 = (const float*)d_in[20];

    const int Nn = in_sizes[0] / 3;
    const int E  = in_sizes[1] / 2;
    float* out = (float*)d_out;

    float *AB, *hcat, *m1, *m2, *wc2, *wc3, *bc2, *bc3;
    unsigned* agg;
    uint4 *wh1, *wl1, *wh2, *wl2, *wh3, *wl3;
    cudaGetSymbolAddress((void**)&AB,   g_AB);
    cudaGetSymbolAddress((void**)&agg,  g_agg);
    cudaGetSymbolAddress((void**)&hcat, g_hcat);
    cudaGetSymbolAddress((void**)&m1,   g_m1);
    cudaGetSymbolAddress((void**)&m2,   g_m2);
    cudaGetSymbolAddress((void**)&wc2,  g_wc2);
    cudaGetSymbolAddress((void**)&wc3,  g_wc3);
    cudaGetSymbolAddress((void**)&bc2,  g_bc2);
    cudaGetSymbolAddress((void**)&bc3,  g_bc3);
    cudaGetSymbolAddress((void**)&wh1,  g_wh1);
    cudaGetSymbolAddress((void**)&wl1,  g_wl1);
    cudaGetSymbolAddress((void**)&wh2,  g_wh2);
    cudaGetSymbolAddress((void**)&wl2,  g_wl2);
    cudaGetSymbolAddress((void**)&wh3,  g_wh3);
    cudaGetSymbolAddress((void**)&wl3,  g_wl3);

    // dynamic smem: 1024 idx + 2*W(BN*144) + 2*A(128*144)
    const int SM1 = 1024 + 2 * (64  * 144) + 2 * 18432;  // 56320
    const int SM2 = 1024 + 2 * (128 * 144) + 2 * 18432;  // 74752
    cudaFuncSetAttribute(edge_mma_kernel<64, 64>,   cudaFuncAttributeMaxDynamicSharedMemorySize, SM1);
    cudaFuncSetAttribute(edge_mma_kernel<128, 128>, cudaFuncAttributeMaxDynamicSharedMemorySize, SM2);
    cudaFuncSetAttribute(edge_mma_kernel<256, 128>, cudaFuncAttributeMaxDynamicSharedMemorySize, SM2);

    const int TB = 256;
    dim3 blk(TB);
    const int gx  = (Nn + 127) / 128;
    const int egx = (E + 127) / 128;

    // launch order puts edge1 at slot 4 (the ncu-profiled launch)
    prep_wb_kernel<<<(64 * 64 + TB - 1) / TB, blk>>>(w1b, wh1, wl1, 64, 64, 64);            // 1
    convert_idx_kernel<<<(E + TB - 1) / TB, blk>>>((const unsigned*)ei, E);                 // 2
    node1_fused_kernel<<<(Nn * 128 + TB - 1) / TB, blk>>>(x, w1a, b1a, AB, agg, Nn);        // 3
    edge_mma_kernel<64, 64><<<dim3(egx, 1), blk, SM1>>>(AB, wh1, wl1, b1b, agg, E, 64);     // 4
    decode_kernel<<<(Nn * 64 + TB - 1) / TB, blk>>>(agg, hcat + 0, Nn * 64, 64, 448);       // 5

    // ---- EdgeConv 2: 64 -> 128 ----
    prep_kernel<<<64, blk>>>(w2a, b2a, wc2, bc2, 64, 128);
    prep_wb_kernel<<<(128 * 128 + TB - 1) / TB, blk>>>(w2b, wh2, wl2, 128, 128, 128);
    sgemm_bias_kernel<false><<<dim3(gx, 2), blk>>>(hcat, 448, wc2, 256, bc2, AB, 256, Nn, 256, 64);
    clear_kernel<<<(Nn * 128 + TB - 1) / TB, blk>>>(agg, Nn * 128);
    edge_mma_kernel<128, 128><<<dim3(egx, 1), blk, SM2>>>(AB, wh2, wl2, b2b, agg, E, 128);
    decode_kernel<<<(Nn * 128 + TB - 1) / TB, blk>>>(agg, hcat + 64, Nn * 128, 128, 448);

    // ---- EdgeConv 3: 128 -> 256 ----
    prep_kernel<<<256, blk>>>(w3a, b3a, wc3, bc3, 128, 256);
    prep_wb_kernel<<<(256 * 256 + TB - 1) / TB, blk>>>(w3b, wh3, wl3, 256, 256, 128);
    sgemm_bias_kernel<false><<<dim3(gx, 4), blk>>>(hcat + 64, 448, wc3, 512, bc3, AB, 512, Nn, 512, 128);
    clear_kernel<<<(Nn * 256 + TB - 1) / TB, blk>>>(agg, Nn * 256);
    edge_mma_kernel<256, 128><<<dim3(egx, 2), blk, SM2>>>(AB, wh3, wl3, b3b, agg, E, 256);
    decode_kernel<<<(Nn * 256 + TB - 1) / TB, blk>>>(agg, hcat + 192, Nn * 256, 256, 448);

    // ---- MLP head ----
    sgemm_bias_kernel<true><<<dim3(gx, 4), blk>>>(hcat, 448, wm1, 512, bm1, m1, 512, Nn, 512, 448);
    sgemm_bias_kernel<true><<<dim3(gx, 2), blk>>>(m1, 512, wm2, 256, bm2, m2, 256, Nn, 256, 512);
    mlp3_kernel<<<(Nn * 32 + TB - 1) / TB, blk>>>(m2, wm3, bm3, out, Nn);
}

// round 6
// speedup vs baseline: 1.3973x; 1.0615x over previous
#include <cuda_runtime.h>
#include <cuda_bf16.h>
#include <cstdint>

// ---------------------------------------------------------------------------
// DGCNN segmentation. Edge GEMMs: mma.sync bf16x3 split precision, ldmatrix
// fragment loads, cp.async W streaming per 64-wide K chunk.
// Node precompute + MLP head: fp32 tiled SGEMM.
//
// EdgeConv:  m = relu([x_i, x_j-x_i] @ W1 + b1) @ W2 + b2
//   per-node AB = [A | B];  per-edge h = relu(A[dst]+B[src]);  m = h@W2+b2;
//   segment-max(dst) via ordered-uint atomicMax.
// ---------------------------------------------------------------------------

#define NMAX 30016
#define EMAX 480256

__device__ float    g_AB[NMAX * 512];
__device__ unsigned g_agg[NMAX * 256];
__device__ float    g_hcat[NMAX * 448];
__device__ float    g_m1[NMAX * 512];
__device__ float    g_m2[NMAX * 256];
__device__ float    g_wc2[64 * 256];
__device__ float    g_wc3[128 * 512];
__device__ float    g_bc2[256];
__device__ float    g_bc3[512];
// W^T bf16 hi/lo, chunked layout: [(tile*NCH + chunk)*BN + n][72] halves
__device__ uint4    g_wh1[64 * 72 / 8],       g_wl1[64 * 72 / 8];
__device__ uint4    g_wh2[2 * 128 * 72 / 8],  g_wl2[2 * 128 * 72 / 8];
__device__ uint4    g_wh3[8 * 128 * 72 / 8],  g_wl3[8 * 128 * 72 / 8];
__device__ int      g_src[EMAX];
__device__ int      g_dst[EMAX];

// ---- ordered-uint encoding for float max ------------------------------------
__device__ __forceinline__ unsigned f2ord(float f) {
    int i = __float_as_int(f);
    return (i >= 0) ? ((unsigned)i | 0x80000000u) : ~(unsigned)i;
}
__device__ __forceinline__ float ord2f(unsigned u) {
    int i = (u & 0x80000000u) ? (int)(u & 0x7fffffffu) : (int)(~u);
    return __int_as_float(i);
}

// ---- PTX helpers --------------------------------------------------------------
__device__ __forceinline__ uint32_t smem_u32(const void* p) {
    uint32_t a;
    asm("{ .reg .u64 t; cvta.to.shared.u64 t, %1; cvt.u32.u64 %0, t; }" : "=r"(a) : "l"(p));
    return a;
}
__device__ __forceinline__ void mma_bf16(float* d, const uint32_t* a,
                                         uint32_t b0, uint32_t b1) {
    asm volatile(
        "mma.sync.aligned.m16n8k16.row.col.f32.bf16.bf16.f32 "
        "{%0,%1,%2,%3},{%4,%5,%6,%7},{%8,%9},{%0,%1,%2,%3};"
        : "+f"(d[0]), "+f"(d[1]), "+f"(d[2]), "+f"(d[3])
        : "r"(a[0]), "r"(a[1]), "r"(a[2]), "r"(a[3]), "r"(b0), "r"(b1));
}
__device__ __forceinline__ void ldsm_x4(uint32_t* r, uint32_t addr) {
    asm volatile("ldmatrix.sync.aligned.m8n8.x4.shared.b16 {%0,%1,%2,%3},[%4];"
                 : "=r"(r[0]), "=r"(r[1]), "=r"(r[2]), "=r"(r[3]) : "r"(addr));
}
__device__ __forceinline__ void cp16(uint32_t s, const void* g) {
    asm volatile("cp.async.ca.shared.global [%0],[%1],16;" :: "r"(s), "l"(g));
}

// ---- edge index convert with inline dtype detection ---------------------------
__global__ void convert_idx_kernel(const unsigned* __restrict__ raw, int E) {
    int n = (E < 256) ? E : 256;
    int is64 = 1;
    for (int i = 0; i < n; i++)
        if (raw[2 * i + 1] != 0u) { is64 = 0; break; }   // int64 high words are 0
    int i = blockIdx.x * blockDim.x + threadIdx.x;
    if (i >= E) return;
    if (is64) {
        const long long* p = (const long long*)raw;
        g_src[i] = (int)p[i];
        g_dst[i] = (int)p[E + i];
    } else {
        const int* p = (const int*)raw;
        g_src[i] = p[i];
        g_dst[i] = p[E + i];
    }
}

// ---- weight prep: wc = [Wtop - Wbot | Wbot], bc = [b | 0] ---------------------
__global__ void prep_kernel(const float* __restrict__ w, const float* __restrict__ b,
                            float* __restrict__ wc, float* __restrict__ bc,
                            int C, int H) {
    int stride = gridDim.x * blockDim.x;
    int i0 = blockIdx.x * blockDim.x + threadIdx.x;
    for (int t = i0; t < C * H; t += stride) {
        int k = t / H, j = t % H;
        float wd = w[(k + C) * H + j];
        wc[k * 2 * H + j]     = w[k * H + j] - wd;
        wc[k * 2 * H + H + j] = wd;
    }
    for (int t = i0; t < H; t += stride) { bc[t] = b[t]; bc[H + t] = 0.f; }
}

// ---- weight prep: W^T bf16 hi/lo chunked [(tile*NCH+c)*BN + n][72] ------------
__global__ void prep_wb_kernel(const float* __restrict__ W,  // [H, COUT] row-major
                               uint4* __restrict__ Whi, uint4* __restrict__ Wlo,
                               int H, int COUT, int BN) {
    int i = blockIdx.x * blockDim.x + threadIdx.x;
    if (i >= H * COUT) return;
    int k = i / COUT, n = i % COUT;
    float w = W[i];
    __nv_bfloat16 hb = __float2bfloat16(w);
    __nv_bfloat16 lb = __float2bfloat16(w - __bfloat162float(hb));
    int NCH = H >> 6;
    int tile = n / BN, nl = n % BN, c = k >> 6, kl = k & 63;
    size_t off = ((size_t)(tile * NCH + c) * BN + nl) * 72 + kl;   // halves
    ((unsigned short*)Whi)[off] = __bfloat16_as_ushort(hb);
    ((unsigned short*)Wlo)[off] = __bfloat16_as_ushort(lb);
}

// ---- layer-1 node precompute fused with wc1 prep + agg clear ------------------
__global__ void node1_fused_kernel(const float* __restrict__ x,
                                   const float* __restrict__ w1a,
                                   const float* __restrict__ b1a,
                                   float* __restrict__ AB,
                                   unsigned* __restrict__ agg, int M) {
    int idx = blockIdx.x * blockDim.x + threadIdx.x;
    if (idx >= M * 128) return;
    if (idx < M * 64) agg[idx] = 0u;
    int n = idx >> 7, j = idx & 127;
    float wk0, wk1, wk2, bb;
    if (j < 64) {
        wk0 = w1a[0 * 64 + j] - w1a[3 * 64 + j];
        wk1 = w1a[1 * 64 + j] - w1a[4 * 64 + j];
        wk2 = w1a[2 * 64 + j] - w1a[5 * 64 + j];
        bb  = b1a[j];
    } else {
        int jj = j - 64;
        wk0 = w1a[3 * 64 + jj];
        wk1 = w1a[4 * 64 + jj];
        wk2 = w1a[5 * 64 + jj];
        bb  = 0.f;
    }
    float x0 = x[n * 3 + 0], x1 = x[n * 3 + 1], x2 = x[n * 3 + 2];
    AB[idx] = fmaf(x0, wk0, fmaf(x1, wk1, fmaf(x2, wk2, bb)));
}

// ---- fp32 tiled SGEMM (node precompute + MLP head) ----------------------------
template <bool RELU>
__global__ void __launch_bounds__(256, 2)
sgemm_bias_kernel(const float* __restrict__ A, int lda,
                  const float* __restrict__ W, int ldw,
                  const float* __restrict__ bias,
                  float* __restrict__ C, int ldc, int M, int N, int K) {
    constexpr int BM = 128, BN = 128, BK = 16;
    __shared__ float As[BK][BM + 4];
    __shared__ float Ws[BK][BN];
    const int tid = threadIdx.x;
    const int bm = blockIdx.x * BM;
    const int bn = blockIdx.y * BN;
    const int rowb = (tid / 16) * 8;
    const int colb = (tid % 16) * 8;
    const int a_m = tid >> 2;
    const int a_k = (tid & 3) * 4;
    const int w_r = tid >> 4;
    const int w_c = (tid & 15) * 8;

    float acc[8][8];
#pragma unroll
    for (int i = 0; i < 8; i++)
#pragma unroll
        for (int j = 0; j < 8; j++) acc[i][j] = 0.f;

    for (int k0 = 0; k0 < K; k0 += BK) {
#pragma unroll
        for (int p = 0; p < 2; p++) {
            int m = a_m + p * 64;
            float4 v = make_float4(0.f, 0.f, 0.f, 0.f);
            if (bm + m < M)
                v = *reinterpret_cast<const float4*>(A + (size_t)(bm + m) * lda + k0 + a_k);
            As[a_k + 0][m] = v.x; As[a_k + 1][m] = v.y;
            As[a_k + 2][m] = v.z; As[a_k + 3][m] = v.w;
        }
#pragma unroll
        for (int q = 0; q < 2; q++)
            *reinterpret_cast<float4*>(&Ws[w_r][w_c + q * 4]) =
                *reinterpret_cast<const float4*>(W + (size_t)(k0 + w_r) * ldw + bn + w_c + q * 4);
        __syncthreads();
#pragma unroll
        for (int kk = 0; kk < BK; kk++) {
            float af[8], wf[8];
#pragma unroll
            for (int i = 0; i < 8; i++) af[i] = As[kk][rowb + i];
#pragma unroll
            for (int j = 0; j < 8; j++) wf[j] = Ws[kk][colb + j];
#pragma unroll
            for (int i = 0; i < 8; i++)
#pragma unroll
                for (int j = 0; j < 8; j++) acc[i][j] = fmaf(af[i], wf[j], acc[i][j]);
        }
        __syncthreads();
    }
#pragma unroll
    for (int i = 0; i < 8; i++) {
        int m = bm + rowb + i;
        if (m >= M) break;
#pragma unroll
        for (int j = 0; j < 8; j++) {
            float v = acc[i][j] + bias[bn + colb + j];
            if (RELU) v = fmaxf(v, 0.f);
            C[(size_t)m * ldc + bn + colb + j] = v;
        }
    }
}

// ---- mma.sync edge kernel: ldmatrix frags, cp.async W, chunked K --------------
// Block: 256 thr = 8 warps (4 m x 2 n). Tile: 128 edges x BN outputs, K = H.
template <int H, int BN, int MINB>
__global__ void __launch_bounds__(256, MINB)
edge_mma_kernel(const float* __restrict__ AB,
                const uint4* __restrict__ Whi_g, const uint4* __restrict__ Wlo_g,
                const float* __restrict__ bias,
                unsigned* __restrict__ agg, int E, int COUT) {
    constexpr int NCH = H / 64;
    constexpr int NA  = BN / 16;            // n atoms per warp
    constexpr int WSZ = BN * 144;           // bytes per W chunk array (pitch 72 halves)
    constexpr int ASZ = 128 * 144;          // bytes per A array
    constexpr int OW  = 1024;
    constexpr int OA  = OW + 2 * WSZ;
    constexpr int WCNT = BN * 9;            // uint4 per W array per chunk

    extern __shared__ char sm[];
    const uint32_t smb = smem_u32(sm);
    int* sdst = (int*)sm;
    int* ssrc = (int*)(sm + 512);

    const int tid = threadIdx.x;
    const int wid = tid >> 5, lane = tid & 31;
    const int g = lane >> 2, tig = lane & 3;
    const int e0 = blockIdx.x * 128;
    const int bn = blockIdx.y * BN;

    if (tid < 128) { int e = e0 + tid; ssrc[tid] = (e < E) ? g_src[e] : 0; }
    else           { int e = e0 + tid - 128; sdst[tid - 128] = (e < E) ? g_dst[e] : 0; }
    __syncthreads();

    const int r  = tid >> 1;          // edge row this thread fills
    const int hf = tid & 1;           // 32-col half of the 64-chunk
    const float* Arow = AB + (size_t)sdst[r] * (2 * H) + hf * 32;
    const float* Brow = AB + (size_t)ssrc[r] * (2 * H) + H + hf * 32;

    const int wm = wid >> 1, wn = wid & 1;
    const int m0 = wm * 32, n0 = wn * (BN / 2);

    // ldmatrix per-lane base offsets (conflict-free: pitch 144 => 16B bank walk)
    const int lr = lane & 7;
    const uint32_t a_off =
        (uint32_t)(m0 + lr + ((lane >> 3) & 1) * 8) * 144u + (uint32_t)(lane >> 4) * 16u;
    const uint32_t w_off =
        (uint32_t)(n0 + lr + ((lane >> 4) & 1) * 8) * 144u + (uint32_t)((lane >> 3) & 1) * 16u;

    const uint32_t WhU = smb + OW;
    const uint32_t WlU = WhU + WSZ;
    const uint32_t AhU = smb + OA;
    const uint32_t AlU = AhU + ASZ;
    char* Ah = sm + OA;
    char* Al = sm + OA + ASZ;

    float acc[2][NA][4];
#pragma unroll
    for (int ma = 0; ma < 2; ma++)
#pragma unroll
        for (int na = 0; na < NA; na++)
#pragma unroll
            for (int q = 0; q < 4; q++) acc[ma][na][q] = 0.f;

    for (int c = 0; c < NCH; c++) {
        if (c) __syncthreads();   // smem reuse barrier

        // ---- W chunk via cp.async (overlaps with A fill below) ----
        {
            const char* shp = (const char*)(Whi_g + (size_t)(blockIdx.y * NCH + c) * WCNT);
            const char* slp = (const char*)(Wlo_g + (size_t)(blockIdx.y * NCH + c) * WCNT);
            for (int i = tid; i < WCNT; i += 256) {
                cp16(WhU + i * 16, shp + i * 16);
                cp16(WlU + i * 16, slp + i * 16);
            }
            asm volatile("cp.async.commit_group;" ::: "memory");
        }
        // ---- fill A hi/lo for this chunk ----
        {
            const float4* Ap = (const float4*)(Arow + c * 64);
            const float4* Bp = (const float4*)(Brow + c * 64);
            float v[32];
#pragma unroll
            for (int q = 0; q < 8; q++) {
                float4 a = Ap[q], b = Bp[q];
                v[q * 4 + 0] = fmaxf(a.x + b.x, 0.f);
                v[q * 4 + 1] = fmaxf(a.y + b.y, 0.f);
                v[q * 4 + 2] = fmaxf(a.z + b.z, 0.f);
                v[q * 4 + 3] = fmaxf(a.w + b.w, 0.f);
            }
            char* ah = Ah + r * 144 + hf * 64;
            char* al = Al + r * 144 + hf * 64;
#pragma unroll
            for (int q8 = 0; q8 < 4; q8++) {
                uint32_t uh[4], ul[4];
#pragma unroll
                for (int p = 0; p < 4; p++) {
                    float v0 = v[q8 * 8 + p * 2], v1 = v[q8 * 8 + p * 2 + 1];
                    __nv_bfloat16 h0 = __float2bfloat16(v0), h1 = __float2bfloat16(v1);
                    __nv_bfloat16 l0 = __float2bfloat16(v0 - __bfloat162float(h0));
                    __nv_bfloat16 l1 = __float2bfloat16(v1 - __bfloat162float(h1));
                    uh[p] = ((uint32_t)__bfloat16_as_ushort(h1) << 16) | __bfloat16_as_ushort(h0);
                    ul[p] = ((uint32_t)__bfloat16_as_ushort(l1) << 16) | __bfloat16_as_ushort(l0);
                }
                *(uint4*)(ah + q8 * 16) = make_uint4(uh[0], uh[1], uh[2], uh[3]);
                *(uint4*)(al + q8 * 16) = make_uint4(ul[0], ul[1], ul[2], ul[3]);
            }
        }
        asm volatile("cp.async.wait_group 0;" ::: "memory");
        __syncthreads();

        // ---- mma over this chunk ----
#pragma unroll
        for (int kq = 0; kq < 4; kq++) {
            uint32_t ah[2][4], al[2][4];
#pragma unroll
            for (int ma = 0; ma < 2; ma++) {
                ldsm_x4(ah[ma], AhU + a_off + (uint32_t)(ma * 16 * 144 + kq * 32));
                ldsm_x4(al[ma], AlU + a_off + (uint32_t)(ma * 16 * 144 + kq * 32));
            }
#pragma unroll
            for (int n2 = 0; n2 < NA / 2; n2++) {
                uint32_t wh[4], wl[4];
                ldsm_x4(wh, WhU + w_off + (uint32_t)(n2 * 16 * 144 + kq * 32));
                ldsm_x4(wl, WlU + w_off + (uint32_t)(n2 * 16 * 144 + kq * 32));
#pragma unroll
                for (int j = 0; j < 2; j++) {
                    const int na = n2 * 2 + j;
                    mma_bf16(acc[0][na], ah[0], wh[2 * j], wh[2 * j + 1]);
                    mma_bf16(acc[1][na], ah[1], wh[2 * j], wh[2 * j + 1]);
                    mma_bf16(acc[0][na], al[0], wh[2 * j], wh[2 * j + 1]);
                    mma_bf16(acc[1][na], al[1], wh[2 * j], wh[2 * j + 1]);
                    mma_bf16(acc[0][na], ah[0], wl[2 * j], wl[2 * j + 1]);
                    mma_bf16(acc[1][na], ah[1], wl[2 * j], wl[2 * j + 1]);
                }
            }
        }
    }

    // ---- epilogue: bias + ordered-uint atomicMax segment-max ----
#pragma unroll
    for (int ma = 0; ma < 2; ma++) {
#pragma unroll
        for (int rr = 0; rr < 2; rr++) {
            const int rloc = m0 + ma * 16 + g + rr * 8;
            if (e0 + rloc >= E) continue;
            const int d = sdst[rloc];
            unsigned* arow = agg + (size_t)d * COUT + bn;
#pragma unroll
            for (int na = 0; na < NA; na++) {
                const int j = n0 + na * 8 + 2 * tig;
                float v0 = acc[ma][na][rr * 2 + 0] + bias[bn + j];
                float v1 = acc[ma][na][rr * 2 + 1] + bias[bn + j + 1];
                unsigned k0 = f2ord(v0);
                if (k0 > arow[j]) atomicMax(arow + j, k0);
                unsigned k1 = f2ord(v1);
                if (k1 > arow[j + 1]) atomicMax(arow + j + 1, k1);
            }
        }
    }
}

// ---- decode agg -> float -------------------------------------------------------
__global__ void decode_kernel(const unsigned* __restrict__ agg,
                              float* __restrict__ dsth, int total, int C, int ldc) {
    int i = blockIdx.x * blockDim.x + threadIdx.x;
    if (i >= total) return;
    int n = i / C, c = i % C;
    unsigned u = agg[i];
    dsth[(size_t)n * ldc + c] = (u == 0u) ? 0.f : ord2f(u);
}
__global__ void clear_kernel(unsigned* __restrict__ p, int n) {
    int i = blockIdx.x * blockDim.x + threadIdx.x;
    if (i < n) p[i] = 0u;
}

// ---- final 256 -> 4 linear ------------------------------------------------------
__global__ void mlp3_kernel(const float* __restrict__ A, const float* __restrict__ W,
                            const float* __restrict__ b, float* __restrict__ out, int M) {
    int gw = (blockIdx.x * blockDim.x + threadIdx.x) >> 5;
    int lane = threadIdx.x & 31;
    if (gw >= M) return;
    const float* a = A + (size_t)gw * 256;
    float acc0 = 0.f, acc1 = 0.f, acc2 = 0.f, acc3 = 0.f;
    for (int k = lane; k < 256; k += 32) {
        float av = a[k];
        const float* wr = W + k * 4;
        acc0 = fmaf(av, wr[0], acc0);
        acc1 = fmaf(av, wr[1], acc1);
        acc2 = fmaf(av, wr[2], acc2);
        acc3 = fmaf(av, wr[3], acc3);
    }
#pragma unroll
    for (int off = 16; off > 0; off >>= 1) {
        acc0 += __shfl_down_sync(0xffffffffu, acc0, off);
        acc1 += __shfl_down_sync(0xffffffffu, acc1, off);
        acc2 += __shfl_down_sync(0xffffffffu, acc2, off);
        acc3 += __shfl_down_sync(0xffffffffu, acc3, off);
    }
    if (lane == 0) {
        out[gw * 4 + 0] = acc0 + b[0];
        out[gw * 4 + 1] = acc1 + b[1];
        out[gw * 4 + 2] = acc2 + b[2];
        out[gw * 4 + 3] = acc3 + b[3];
    }
}

// ---------------------------------------------------------------------------
extern "C" void kernel_launch(void* const* d_in, const int* in_sizes, int n_in,
                              void* d_out, int out_size) {
    const float* x   = (const float*)d_in[0];
    const void*  ei  = d_in[1];
    const float* w1a = (const float*)d_in[3];
    const float* b1a = (const float*)d_in[4];
    const float* w1b = (const float*)d_in[5];
    const float* b1b = (const float*)d_in[6];
    const float* w2a = (const float*)d_in[7];
    const float* b2a = (const float*)d_in[8];
    const float* w2b = (const float*)d_in[9];
    const float* b2b = (const float*)d_in[10];
    const float* w3a = (const float*)d_in[11];
    const float* b3a = (const float*)d_in[12];
    const float* w3b = (const float*)d_in[13];
    const float* b3b = (const float*)d_in[14];
    const float* wm1 = (const float*)d_in[15];
    const float* bm1 = (const float*)d_in[16];
    const float* wm2 = (const float*)d_in[17];
    const float* bm2 = (const float*)d_in[18];
    const float* wm3 = (const float*)d_in[19];
    const float* bm3 = (const float*)d_in[20];

    const int Nn = in_sizes[0] / 3;
    const int E  = in_sizes[1] / 2;
    float* out = (float*)d_out;

    float *AB, *hcat, *m1, *m2, *wc2, *wc3, *bc2, *bc3;
    unsigned* agg;
    uint4 *wh1, *wl1, *wh2, *wl2, *wh3, *wl3;
    cudaGetSymbolAddress((void**)&AB,   g_AB);
    cudaGetSymbolAddress((void**)&agg,  g_agg);
    cudaGetSymbolAddress((void**)&hcat, g_hcat);
    cudaGetSymbolAddress((void**)&m1,   g_m1);
    cudaGetSymbolAddress((void**)&m2,   g_m2);
    cudaGetSymbolAddress((void**)&wc2,  g_wc2);
    cudaGetSymbolAddress((void**)&wc3,  g_wc3);
    cudaGetSymbolAddress((void**)&bc2,  g_bc2);
    cudaGetSymbolAddress((void**)&bc3,  g_bc3);
    cudaGetSymbolAddress((void**)&wh1,  g_wh1);
    cudaGetSymbolAddress((void**)&wl1,  g_wl1);
    cudaGetSymbolAddress((void**)&wh2,  g_wh2);
    cudaGetSymbolAddress((void**)&wl2,  g_wl2);
    cudaGetSymbolAddress((void**)&wh3,  g_wh3);
    cudaGetSymbolAddress((void**)&wl3,  g_wl3);

    // dynamic smem: 1024 idx + 2*W(BN*144) + 2*A(128*144)
    const int SM1 = 1024 + 2 * (64  * 144) + 2 * 18432;  // 56320
    const int SM2 = 1024 + 2 * (128 * 144) + 2 * 18432;  // 74752
    cudaFuncSetAttribute(edge_mma_kernel<64, 64, 3>,    cudaFuncAttributeMaxDynamicSharedMemorySize, SM1);
    cudaFuncSetAttribute(edge_mma_kernel<128, 128, 2>,  cudaFuncAttributeMaxDynamicSharedMemorySize, SM2);
    cudaFuncSetAttribute(edge_mma_kernel<256, 128, 2>,  cudaFuncAttributeMaxDynamicSharedMemorySize, SM2);

    const int TB = 256;
    dim3 blk(TB);
    const int gx  = (Nn + 127) / 128;
    const int egx = (E + 127) / 128;

    // launch order puts edge1 at slot 4 (the ncu-profiled launch)
    prep_wb_kernel<<<(64 * 64 + TB - 1) / TB, blk>>>(w1b, wh1, wl1, 64, 64, 64);              // 1
    convert_idx_kernel<<<(E + TB - 1) / TB, blk>>>((const unsigned*)ei, E);                   // 2
    node1_fused_kernel<<<(Nn * 128 + TB - 1) / TB, blk>>>(x, w1a, b1a, AB, agg, Nn);          // 3
    edge_mma_kernel<64, 64, 3><<<dim3(egx, 1), blk, SM1>>>(AB, wh1, wl1, b1b, agg, E, 64);    // 4
    decode_kernel<<<(Nn * 64 + TB - 1) / TB, blk>>>(agg, hcat + 0, Nn * 64, 64, 448);         // 5

    // ---- EdgeConv 2: 64 -> 128 ----
    prep_kernel<<<64, blk>>>(w2a, b2a, wc2, bc2, 64, 128);
    prep_wb_kernel<<<(128 * 128 + TB - 1) / TB, blk>>>(w2b, wh2, wl2, 128, 128, 128);
    sgemm_bias_kernel<false><<<dim3(gx, 2), blk>>>(hcat, 448, wc2, 256, bc2, AB, 256, Nn, 256, 64);
    clear_kernel<<<(Nn * 128 + TB - 1) / TB, blk>>>(agg, Nn * 128);
    edge_mma_kernel<128, 128, 2><<<dim3(egx, 1), blk, SM2>>>(AB, wh2, wl2, b2b, agg, E, 128);
    decode_kernel<<<(Nn * 128 + TB - 1) / TB, blk>>>(agg, hcat + 64, Nn * 128, 128, 448);

    // ---- EdgeConv 3: 128 -> 256 ----
    prep_kernel<<<256, blk>>>(w3a, b3a, wc3, bc3, 128, 256);
    prep_wb_kernel<<<(256 * 256 + TB - 1) / TB, blk>>>(w3b, wh3, wl3, 256, 256, 128);
    sgemm_bias_kernel<false><<<dim3(gx, 4), blk>>>(hcat + 64, 448, wc3, 512, bc3, AB, 512, Nn, 512, 128);
    clear_kernel<<<(Nn * 256 + TB - 1) / TB, blk>>>(agg, Nn * 256);
    edge_mma_kernel<256, 128, 2><<<dim3(egx, 2), blk, SM2>>>(AB, wh3, wl3, b3b, agg, E, 256);
    decode_kernel<<<(Nn * 256 + TB - 1) / TB, blk>>>(agg, hcat + 192, Nn * 256, 256, 448);

    // ---- MLP head ----
    sgemm_bias_kernel<true><<<dim3(gx, 4), blk>>>(hcat, 448, wm1, 512, bm1, m1, 512, Nn, 512, 448);
    sgemm_bias_kernel<true><<<dim3(gx, 2), blk>>>(m1, 512, wm2, 256, bm2, m2, 256, Nn, 256, 512);
    mlp3_kernel<<<(Nn * 32 + TB - 1) / TB, blk>>>(m2, wm3, bm3, out, Nn);
}

// round 7
// speedup vs baseline: 2.0722x; 1.4830x over previous
#include <cuda_runtime.h>
#include <cuda_bf16.h>
#include <cstdint>

// ---------------------------------------------------------------------------
// DGCNN segmentation. ALL GEMMs on tensor cores via mma.sync bf16x3 split
// precision (ldmatrix frags, cp.async W streaming, 64-wide K chunks).
//   edge_mma_kernel : gather relu(A[dst]+B[src]) tiles -> GEMM -> atomicMax
//   dense_mma_kernel: plain  C = act(A @ W + b)  (node precompute + MLP head)
// ---------------------------------------------------------------------------

#define NMAX 30016
#define EMAX 480256

__device__ float    g_AB[NMAX * 512];
__device__ unsigned g_agg[NMAX * 256];
__device__ float    g_hcat[NMAX * 448];
__device__ float    g_m1[NMAX * 512];
__device__ float    g_m2[NMAX * 256];
__device__ float    g_wc2[64 * 256];
__device__ float    g_wc3[128 * 512];
__device__ float    g_bc2[256];
__device__ float    g_bc3[512];
// W^T bf16 hi/lo, chunked layout: [(tile*NCH + chunk)*BN + n][72] halves
__device__ uint4    g_wh1[64 * 72 / 8],       g_wl1[64 * 72 / 8];
__device__ uint4    g_wh2[2 * 128 * 72 / 8],  g_wl2[2 * 128 * 72 / 8];
__device__ uint4    g_wh3[8 * 128 * 72 / 8],  g_wl3[8 * 128 * 72 / 8];
__device__ uint4    g_whn2[2304],  g_wln2[2304];     // wc2:  2 tiles x 1 ch
__device__ uint4    g_whn3[9216],  g_wln3[9216];     // wc3:  4 tiles x 2 ch
__device__ uint4    g_whm1[32256], g_wlm1[32256];    // wm1:  4 tiles x 7 ch
__device__ uint4    g_whm2[18432], g_wlm2[18432];    // wm2:  2 tiles x 8 ch
__device__ int      g_src[EMAX];
__device__ int      g_dst[EMAX];

// ---- ordered-uint encoding for float max ------------------------------------
__device__ __forceinline__ unsigned f2ord(float f) {
    int i = __float_as_int(f);
    return (i >= 0) ? ((unsigned)i | 0x80000000u) : ~(unsigned)i;
}
__device__ __forceinline__ float ord2f(unsigned u) {
    int i = (u & 0x80000000u) ? (int)(u & 0x7fffffffu) : (int)(~u);
    return __int_as_float(i);
}

// ---- PTX helpers --------------------------------------------------------------
__device__ __forceinline__ uint32_t smem_u32(const void* p) {
    uint32_t a;
    asm("{ .reg .u64 t; cvta.to.shared.u64 t, %1; cvt.u32.u64 %0, t; }" : "=r"(a) : "l"(p));
    return a;
}
__device__ __forceinline__ void mma_bf16(float* d, const uint32_t* a,
                                         uint32_t b0, uint32_t b1) {
    asm volatile(
        "mma.sync.aligned.m16n8k16.row.col.f32.bf16.bf16.f32 "
        "{%0,%1,%2,%3},{%4,%5,%6,%7},{%8,%9},{%0,%1,%2,%3};"
        : "+f"(d[0]), "+f"(d[1]), "+f"(d[2]), "+f"(d[3])
        : "r"(a[0]), "r"(a[1]), "r"(a[2]), "r"(a[3]), "r"(b0), "r"(b1));
}
__device__ __forceinline__ void ldsm_x4(uint32_t* r, uint32_t addr) {
    asm volatile("ldmatrix.sync.aligned.m8n8.x4.shared.b16 {%0,%1,%2,%3},[%4];"
                 : "=r"(r[0]), "=r"(r[1]), "=r"(r[2]), "=r"(r[3]) : "r"(addr));
}
__device__ __forceinline__ void cp16(uint32_t s, const void* g) {
    asm volatile("cp.async.ca.shared.global [%0],[%1],16;" :: "r"(s), "l"(g));
}
// split two fp32 into packed bf16 hi / lo words (lo = exact residual)
__device__ __forceinline__ void split2(float m0, float m1, uint32_t& hi2, uint32_t& lo2) {
    asm("cvt.rn.bf16x2.f32 %0, %1, %2;" : "=r"(hi2) : "f"(m1), "f"(m0));
    float h0 = __uint_as_float(hi2 << 16);
    float h1 = __uint_as_float(hi2 & 0xffff0000u);
    float l0 = m0 - h0, l1 = m1 - h1;
    asm("cvt.rn.bf16x2.f32 %0, %1, %2;" : "=r"(lo2) : "f"(l1), "f"(l0));
}

// ---- edge index convert with inline dtype detection ---------------------------
__global__ void convert_idx_kernel(const unsigned* __restrict__ raw, int E) {
    int n = (E < 256) ? E : 256;
    int is64 = 1;
    for (int i = 0; i < n; i++)
        if (raw[2 * i + 1] != 0u) { is64 = 0; break; }   // int64 high words are 0
    int i = blockIdx.x * blockDim.x + threadIdx.x;
    if (i >= E) return;
    if (is64) {
        const long long* p = (const long long*)raw;
        g_src[i] = (int)p[i];
        g_dst[i] = (int)p[E + i];
    } else {
        const int* p = (const int*)raw;
        g_src[i] = p[i];
        g_dst[i] = p[E + i];
    }
}

// ---- weight prep: wc = [Wtop - Wbot | Wbot], bc = [b | 0] ---------------------
__global__ void prep_kernel(const float* __restrict__ w, const float* __restrict__ b,
                            float* __restrict__ wc, float* __restrict__ bc,
                            int C, int H) {
    int stride = gridDim.x * blockDim.x;
    int i0 = blockIdx.x * blockDim.x + threadIdx.x;
    for (int t = i0; t < C * H; t += stride) {
        int k = t / H, j = t % H;
        float wd = w[(k + C) * H + j];
        wc[k * 2 * H + j]     = w[k * H + j] - wd;
        wc[k * 2 * H + H + j] = wd;
    }
    for (int t = i0; t < H; t += stride) { bc[t] = b[t]; bc[H + t] = 0.f; }
}

// ---- weight prep: W^T bf16 hi/lo chunked [(tile*NCH+c)*BN + n][72] ------------
__global__ void prep_wb_kernel(const float* __restrict__ W,  // [H, COUT] row-major
                               uint4* __restrict__ Whi, uint4* __restrict__ Wlo,
                               int H, int COUT, int BN) {
    int i = blockIdx.x * blockDim.x + threadIdx.x;
    if (i >= H * COUT) return;
    int k = i / COUT, n = i % COUT;
    float w = W[i];
    __nv_bfloat16 hb = __float2bfloat16(w);
    __nv_bfloat16 lb = __float2bfloat16(w - __bfloat162float(hb));
    int NCH = H >> 6;
    int tile = n / BN, nl = n % BN, c = k >> 6, kl = k & 63;
    size_t off = ((size_t)(tile * NCH + c) * BN + nl) * 72 + kl;   // halves
    ((unsigned short*)Whi)[off] = __bfloat16_as_ushort(hb);
    ((unsigned short*)Wlo)[off] = __bfloat16_as_ushort(lb);
}

// ---- layer-1 node precompute fused with wc1 prep + agg clear ------------------
__global__ void node1_fused_kernel(const float* __restrict__ x,
                                   const float* __restrict__ w1a,
                                   const float* __restrict__ b1a,
                                   float* __restrict__ AB,
                                   unsigned* __restrict__ agg, int M) {
    int idx = blockIdx.x * blockDim.x + threadIdx.x;
    if (idx >= M * 128) return;
    if (idx < M * 64) agg[idx] = 0u;
    int n = idx >> 7, j = idx & 127;
    float wk0, wk1, wk2, bb;
    if (j < 64) {
        wk0 = w1a[0 * 64 + j] - w1a[3 * 64 + j];
        wk1 = w1a[1 * 64 + j] - w1a[4 * 64 + j];
        wk2 = w1a[2 * 64 + j] - w1a[5 * 64 + j];
        bb  = b1a[j];
    } else {
        int jj = j - 64;
        wk0 = w1a[3 * 64 + jj];
        wk1 = w1a[4 * 64 + jj];
        wk2 = w1a[5 * 64 + jj];
        bb  = 0.f;
    }
    float x0 = x[n * 3 + 0], x1 = x[n * 3 + 1], x2 = x[n * 3 + 2];
    AB[idx] = fmaf(x0, wk0, fmaf(x1, wk1, fmaf(x2, wk2, bb)));
}

// ---- dense bf16x3 mma GEMM: C = act(A[M,K] @ W[K,N] + bias) -------------------
// Block: 256 thr = 8 warps (4m x 2n). Tile: 128 rows x BN cols, K chunked by 64.
template <int K, int BN, bool RELU>
__global__ void __launch_bounds__(256, 2)
dense_mma_kernel(const float* __restrict__ A, int lda,
                 const uint4* __restrict__ Whi_g, const uint4* __restrict__ Wlo_g,
                 const float* __restrict__ bias,
                 float* __restrict__ C, int ldc, int M) {
    constexpr int NCH = K / 64;
    constexpr int NA  = BN / 16;
    constexpr int WSZ = BN * 144;
    constexpr int ASZ = 128 * 144;
    constexpr int OA  = 2 * WSZ;
    constexpr int WCNT = BN * 9;

    extern __shared__ char sm[];
    const uint32_t smb = smem_u32(sm);

    const int tid = threadIdx.x;
    const int wid = tid >> 5, lane = tid & 31;
    const int g = lane >> 2, tig = lane & 3;
    const int bm = blockIdx.x * 128;
    const int bn = blockIdx.y * BN;

    const int r  = tid >> 1;
    const int hf = tid & 1;
    const bool rv = (bm + r) < M;
    const float* Arow = A + (size_t)(bm + r) * lda + hf * 32;

    const int wm = wid >> 1, wn = wid & 1;
    const int m0 = wm * 32, n0 = wn * (BN / 2);

    const int lr = lane & 7;
    const uint32_t a_off =
        (uint32_t)(m0 + lr + ((lane >> 3) & 1) * 8) * 144u + (uint32_t)(lane >> 4) * 16u;
    const uint32_t w_off =
        (uint32_t)(n0 + lr + ((lane >> 4) & 1) * 8) * 144u + (uint32_t)((lane >> 3) & 1) * 16u;

    const uint32_t WhU = smb;
    const uint32_t WlU = WhU + WSZ;
    const uint32_t AhU = smb + OA;
    const uint32_t AlU = AhU + ASZ;
    char* Ah = sm + OA;
    char* Al = sm + OA + ASZ;

    float acc[2][NA][4];
#pragma unroll
    for (int ma = 0; ma < 2; ma++)
#pragma unroll
        for (int na = 0; na < NA; na++)
#pragma unroll
            for (int q = 0; q < 4; q++) acc[ma][na][q] = 0.f;

    for (int c = 0; c < NCH; c++) {
        if (c) __syncthreads();
        {
            const char* shp = (const char*)(Whi_g + (size_t)(blockIdx.y * NCH + c) * WCNT);
            const char* slp = (const char*)(Wlo_g + (size_t)(blockIdx.y * NCH + c) * WCNT);
            for (int i = tid; i < WCNT; i += 256) {
                cp16(WhU + i * 16, shp + i * 16);
                cp16(WlU + i * 16, slp + i * 16);
            }
            asm volatile("cp.async.commit_group;" ::: "memory");
        }
        {
            const float4* Ap = (const float4*)(Arow + c * 64);
            float v[32];
            if (rv) {
#pragma unroll
                for (int q = 0; q < 8; q++) {
                    float4 a = Ap[q];
                    v[q * 4 + 0] = a.x; v[q * 4 + 1] = a.y;
                    v[q * 4 + 2] = a.z; v[q * 4 + 3] = a.w;
                }
            } else {
#pragma unroll
                for (int q = 0; q < 32; q++) v[q] = 0.f;
            }
            char* ah = Ah + r * 144 + hf * 64;
            char* al = Al + r * 144 + hf * 64;
#pragma unroll
            for (int q8 = 0; q8 < 4; q8++) {
                uint32_t uh[4], ul[4];
#pragma unroll
                for (int p = 0; p < 4; p++)
                    split2(v[q8 * 8 + p * 2], v[q8 * 8 + p * 2 + 1], uh[p], ul[p]);
                *(uint4*)(ah + q8 * 16) = make_uint4(uh[0], uh[1], uh[2], uh[3]);
                *(uint4*)(al + q8 * 16) = make_uint4(ul[0], ul[1], ul[2], ul[3]);
            }
        }
        asm volatile("cp.async.wait_group 0;" ::: "memory");
        __syncthreads();

#pragma unroll
        for (int kq = 0; kq < 4; kq++) {
            uint32_t ah[2][4], al[2][4];
#pragma unroll
            for (int ma = 0; ma < 2; ma++) {
                ldsm_x4(ah[ma], AhU + a_off + (uint32_t)(ma * 16 * 144 + kq * 32));
                ldsm_x4(al[ma], AlU + a_off + (uint32_t)(ma * 16 * 144 + kq * 32));
            }
#pragma unroll
            for (int n2 = 0; n2 < NA / 2; n2++) {
                uint32_t wh[4], wl[4];
                ldsm_x4(wh, WhU + w_off + (uint32_t)(n2 * 16 * 144 + kq * 32));
                ldsm_x4(wl, WlU + w_off + (uint32_t)(n2 * 16 * 144 + kq * 32));
#pragma unroll
                for (int j = 0; j < 2; j++) {
                    const int na = n2 * 2 + j;
                    mma_bf16(acc[0][na], ah[0], wh[2 * j], wh[2 * j + 1]);
                    mma_bf16(acc[1][na], ah[1], wh[2 * j], wh[2 * j + 1]);
                    mma_bf16(acc[0][na], al[0], wh[2 * j], wh[2 * j + 1]);
                    mma_bf16(acc[1][na], al[1], wh[2 * j], wh[2 * j + 1]);
                    mma_bf16(acc[0][na], ah[0], wl[2 * j], wl[2 * j + 1]);
                    mma_bf16(acc[1][na], ah[1], wl[2 * j], wl[2 * j + 1]);
                }
            }
        }
    }

    // ---- epilogue: bias (+relu) -> global f32 ----
#pragma unroll
    for (int ma = 0; ma < 2; ma++) {
#pragma unroll
        for (int rr = 0; rr < 2; rr++) {
            const int rg = bm + m0 + ma * 16 + g + rr * 8;
            if (rg >= M) continue;
            float* crow = C + (size_t)rg * ldc + bn;
#pragma unroll
            for (int na = 0; na < NA; na++) {
                const int j = n0 + na * 8 + 2 * tig;
                float v0 = acc[ma][na][rr * 2 + 0] + bias[bn + j];
                float v1 = acc[ma][na][rr * 2 + 1] + bias[bn + j + 1];
                if (RELU) { v0 = fmaxf(v0, 0.f); v1 = fmaxf(v1, 0.f); }
                *(float2*)(crow + j) = make_float2(v0, v1);
            }
        }
    }
}

// ---- mma.sync edge kernel: ldmatrix frags, cp.async W, chunked K --------------
template <int H, int BN, int MINB>
__global__ void __launch_bounds__(256, MINB)
edge_mma_kernel(const float* __restrict__ AB,
                const uint4* __restrict__ Whi_g, const uint4* __restrict__ Wlo_g,
                const float* __restrict__ bias,
                unsigned* __restrict__ agg, int E, int COUT) {
    constexpr int NCH = H / 64;
    constexpr int NA  = BN / 16;
    constexpr int WSZ = BN * 144;
    constexpr int ASZ = 128 * 144;
    constexpr int OW  = 1024;
    constexpr int OA  = OW + 2 * WSZ;
    constexpr int WCNT = BN * 9;

    extern __shared__ char sm[];
    const uint32_t smb = smem_u32(sm);
    int* sdst = (int*)sm;
    int* ssrc = (int*)(sm + 512);

    const int tid = threadIdx.x;
    const int wid = tid >> 5, lane = tid & 31;
    const int g = lane >> 2, tig = lane & 3;
    const int e0 = blockIdx.x * 128;
    const int bn = blockIdx.y * BN;

    if (tid < 128) { int e = e0 + tid; ssrc[tid] = (e < E) ? g_src[e] : 0; }
    else           { int e = e0 + tid - 128; sdst[tid - 128] = (e < E) ? g_dst[e] : 0; }
    __syncthreads();

    const int r  = tid >> 1;
    const int hf = tid & 1;
    const float* Arow = AB + (size_t)sdst[r] * (2 * H) + hf * 32;
    const float* Brow = AB + (size_t)ssrc[r] * (2 * H) + H + hf * 32;

    const int wm = wid >> 1, wn = wid & 1;
    const int m0 = wm * 32, n0 = wn * (BN / 2);

    const int lr = lane & 7;
    const uint32_t a_off =
        (uint32_t)(m0 + lr + ((lane >> 3) & 1) * 8) * 144u + (uint32_t)(lane >> 4) * 16u;
    const uint32_t w_off =
        (uint32_t)(n0 + lr + ((lane >> 4) & 1) * 8) * 144u + (uint32_t)((lane >> 3) & 1) * 16u;

    const uint32_t WhU = smb + OW;
    const uint32_t WlU = WhU + WSZ;
    const uint32_t AhU = smb + OA;
    const uint32_t AlU = AhU + ASZ;
    char* Ah = sm + OA;
    char* Al = sm + OA + ASZ;

    float acc[2][NA][4];
#pragma unroll
    for (int ma = 0; ma < 2; ma++)
#pragma unroll
        for (int na = 0; na < NA; na++)
#pragma unroll
            for (int q = 0; q < 4; q++) acc[ma][na][q] = 0.f;

    for (int c = 0; c < NCH; c++) {
        if (c) __syncthreads();
        {
            const char* shp = (const char*)(Whi_g + (size_t)(blockIdx.y * NCH + c) * WCNT);
            const char* slp = (const char*)(Wlo_g + (size_t)(blockIdx.y * NCH + c) * WCNT);
            for (int i = tid; i < WCNT; i += 256) {
                cp16(WhU + i * 16, shp + i * 16);
                cp16(WlU + i * 16, slp + i * 16);
            }
            asm volatile("cp.async.commit_group;" ::: "memory");
        }
        {
            const float4* Ap = (const float4*)(Arow + c * 64);
            const float4* Bp = (const float4*)(Brow + c * 64);
            float v[32];
#pragma unroll
            for (int q = 0; q < 8; q++) {
                float4 a = Ap[q], b = Bp[q];
                v[q * 4 + 0] = fmaxf(a.x + b.x, 0.f);
                v[q * 4 + 1] = fmaxf(a.y + b.y, 0.f);
                v[q * 4 + 2] = fmaxf(a.z + b.z, 0.f);
                v[q * 4 + 3] = fmaxf(a.w + b.w, 0.f);
            }
            char* ah = Ah + r * 144 + hf * 64;
            char* al = Al + r * 144 + hf * 64;
#pragma unroll
            for (int q8 = 0; q8 < 4; q8++) {
                uint32_t uh[4], ul[4];
#pragma unroll
                for (int p = 0; p < 4; p++)
                    split2(v[q8 * 8 + p * 2], v[q8 * 8 + p * 2 + 1], uh[p], ul[p]);
                *(uint4*)(ah + q8 * 16) = make_uint4(uh[0], uh[1], uh[2], uh[3]);
                *(uint4*)(al + q8 * 16) = make_uint4(ul[0], ul[1], ul[2], ul[3]);
            }
        }
        asm volatile("cp.async.wait_group 0;" ::: "memory");
        __syncthreads();

#pragma unroll
        for (int kq = 0; kq < 4; kq++) {
            uint32_t ah[2][4], al[2][4];
#pragma unroll
            for (int ma = 0; ma < 2; ma++) {
                ldsm_x4(ah[ma], AhU + a_off + (uint32_t)(ma * 16 * 144 + kq * 32));
                ldsm_x4(al[ma], AlU + a_off + (uint32_t)(ma * 16 * 144 + kq * 32));
            }
#pragma unroll
            for (int n2 = 0; n2 < NA / 2; n2++) {
                uint32_t wh[4], wl[4];
                ldsm_x4(wh, WhU + w_off + (uint32_t)(n2 * 16 * 144 + kq * 32));
                ldsm_x4(wl, WlU + w_off + (uint32_t)(n2 * 16 * 144 + kq * 32));
#pragma unroll
                for (int j = 0; j < 2; j++) {
                    const int na = n2 * 2 + j;
                    mma_bf16(acc[0][na], ah[0], wh[2 * j], wh[2 * j + 1]);
                    mma_bf16(acc[1][na], ah[1], wh[2 * j], wh[2 * j + 1]);
                    mma_bf16(acc[0][na], al[0], wh[2 * j], wh[2 * j + 1]);
                    mma_bf16(acc[1][na], al[1], wh[2 * j], wh[2 * j + 1]);
                    mma_bf16(acc[0][na], ah[0], wl[2 * j], wl[2 * j + 1]);
                    mma_bf16(acc[1][na], ah[1], wl[2 * j], wl[2 * j + 1]);
                }
            }
        }
    }

    // ---- epilogue: bias + vectorized guard + atomicMax segment-max ----
#pragma unroll
    for (int ma = 0; ma < 2; ma++) {
#pragma unroll
        for (int rr = 0; rr < 2; rr++) {
            const int rloc = m0 + ma * 16 + g + rr * 8;
            if (e0 + rloc >= E) continue;
            const int d = sdst[rloc];
            unsigned* arow = agg + (size_t)d * COUT + bn;
#pragma unroll
            for (int na = 0; na < NA; na++) {
                const int j = n0 + na * 8 + 2 * tig;
                float v0 = acc[ma][na][rr * 2 + 0] + bias[bn + j];
                float v1 = acc[ma][na][rr * 2 + 1] + bias[bn + j + 1];
                unsigned k0 = f2ord(v0);
                unsigned k1 = f2ord(v1);
                uint2 cur = *(const uint2*)(arow + j);   // stale-safe (monotonic)
                if (k0 > cur.x) atomicMax(arow + j, k0);
                if (k1 > cur.y) atomicMax(arow + j + 1, k1);
            }
        }
    }
}

// ---- decode agg -> float -------------------------------------------------------
__global__ void decode_kernel(const unsigned* __restrict__ agg,
                              float* __restrict__ dsth, int total, int C, int ldc) {
    int i = blockIdx.x * blockDim.x + threadIdx.x;
    if (i >= total) return;
    int n = i / C, c = i % C;
    unsigned u = agg[i];
    dsth[(size_t)n * ldc + c] = (u == 0u) ? 0.f : ord2f(u);
}
__global__ void clear_kernel(unsigned* __restrict__ p, int n) {
    int i = blockIdx.x * blockDim.x + threadIdx.x;
    if (i < n) p[i] = 0u;
}

// ---- final 256 -> 4 linear ------------------------------------------------------
__global__ void mlp3_kernel(const float* __restrict__ A, const float* __restrict__ W,
                            const float* __restrict__ b, float* __restrict__ out, int M) {
    int gw = (blockIdx.x * blockDim.x + threadIdx.x) >> 5;
    int lane = threadIdx.x & 31;
    if (gw >= M) return;
    const float* a = A + (size_t)gw * 256;
    float acc0 = 0.f, acc1 = 0.f, acc2 = 0.f, acc3 = 0.f;
    for (int k = lane; k < 256; k += 32) {
        float av = a[k];
        const float* wr = W + k * 4;
        acc0 = fmaf(av, wr[0], acc0);
        acc1 = fmaf(av, wr[1], acc1);
        acc2 = fmaf(av, wr[2], acc2);
        acc3 = fmaf(av, wr[3], acc3);
    }
#pragma unroll
    for (int off = 16; off > 0; off >>= 1) {
        acc0 += __shfl_down_sync(0xffffffffu, acc0, off);
        acc1 += __shfl_down_sync(0xffffffffu, acc1, off);
        acc2 += __shfl_down_sync(0xffffffffu, acc2, off);
        acc3 += __shfl_down_sync(0xffffffffu, acc3, off);
    }
    if (lane == 0) {
        out[gw * 4 + 0] = acc0 + b[0];
        out[gw * 4 + 1] = acc1 + b[1];
        out[gw * 4 + 2] = acc2 + b[2];
        out[gw * 4 + 3] = acc3 + b[3];
    }
}

// ---------------------------------------------------------------------------
extern "C" void kernel_launch(void* const* d_in, const int* in_sizes, int n_in,
                              void* d_out, int out_size) {
    const float* x   = (const float*)d_in[0];
    const void*  ei  = d_in[1];
    const float* w1a = (const float*)d_in[3];
    const float* b1a = (const float*)d_in[4];
    const float* w1b = (const float*)d_in[5];
    const float* b1b = (const float*)d_in[6];
    const float* w2a = (const float*)d_in[7];
    const float* b2a = (const float*)d_in[8];
    const float* w2b = (const float*)d_in[9];
    const float* b2b = (const float*)d_in[10];
    const float* w3a = (const float*)d_in[11];
    const float* b3a = (const float*)d_in[12];
    const float* w3b = (const float*)d_in[13];
    const float* b3b = (const float*)d_in[14];
    const float* wm1 = (const float*)d_in[15];
    const float* bm1 = (const float*)d_in[16];
    const float* wm2 = (const float*)d_in[17];
    const float* bm2 = (const float*)d_in[18];
    const float* wm3 = (const float*)d_in[19];
    const float* bm3 = (const float*)d_in[20];

    const int Nn = in_sizes[0] / 3;
    const int E  = in_sizes[1] / 2;
    float* out = (float*)d_out;

    float *AB, *hcat, *m1, *m2, *wc2, *wc3, *bc2, *bc3;
    unsigned* agg;
    uint4 *wh1, *wl1, *wh2, *wl2, *wh3, *wl3;
    uint4 *whn2, *wln2, *whn3, *wln3, *whm1, *wlm1, *whm2, *wlm2;
    cudaGetSymbolAddress((void**)&AB,   g_AB);
    cudaGetSymbolAddress((void**)&agg,  g_agg);
    cudaGetSymbolAddress((void**)&hcat, g_hcat);
    cudaGetSymbolAddress((void**)&m1,   g_m1);
    cudaGetSymbolAddress((void**)&m2,   g_m2);
    cudaGetSymbolAddress((void**)&wc2,  g_wc2);
    cudaGetSymbolAddress((void**)&wc3,  g_wc3);
    cudaGetSymbolAddress((void**)&bc2,  g_bc2);
    cudaGetSymbolAddress((void**)&bc3,  g_bc3);
    cudaGetSymbolAddress((void**)&wh1,  g_wh1);
    cudaGetSymbolAddress((void**)&wl1,  g_wl1);
    cudaGetSymbolAddress((void**)&wh2,  g_wh2);
    cudaGetSymbolAddress((void**)&wl2,  g_wl2);
    cudaGetSymbolAddress((void**)&wh3,  g_wh3);
    cudaGetSymbolAddress((void**)&wl3,  g_wl3);
    cudaGetSymbolAddress((void**)&whn2, g_whn2);
    cudaGetSymbolAddress((void**)&wln2, g_wln2);
    cudaGetSymbolAddress((void**)&whn3, g_whn3);
    cudaGetSymbolAddress((void**)&wln3, g_wln3);
    cudaGetSymbolAddress((void**)&whm1, g_whm1);
    cudaGetSymbolAddress((void**)&wlm1, g_wlm1);
    cudaGetSymbolAddress((void**)&whm2, g_whm2);
    cudaGetSymbolAddress((void**)&wlm2, g_wlm2);

    const int SM1 = 1024 + 2 * (64  * 144) + 2 * 18432;  // 56320
    const int SM2 = 1024 + 2 * (128 * 144) + 2 * 18432;  // 74752
    const int SMD = 2 * (128 * 144) + 2 * 18432;         // 73728
    cudaFuncSetAttribute(edge_mma_kernel<64, 64, 3>,   cudaFuncAttributeMaxDynamicSharedMemorySize, SM1);
    cudaFuncSetAttribute(edge_mma_kernel<128, 128, 2>, cudaFuncAttributeMaxDynamicSharedMemorySize, SM2);
    cudaFuncSetAttribute(edge_mma_kernel<256, 128, 2>, cudaFuncAttributeMaxDynamicSharedMemorySize, SM2);
    cudaFuncSetAttribute(dense_mma_kernel<64,  128, false>, cudaFuncAttributeMaxDynamicSharedMemorySize, SMD);
    cudaFuncSetAttribute(dense_mma_kernel<128, 128, false>, cudaFuncAttributeMaxDynamicSharedMemorySize, SMD);
    cudaFuncSetAttribute(dense_mma_kernel<448, 128, true>,  cudaFuncAttributeMaxDynamicSharedMemorySize, SMD);
    cudaFuncSetAttribute(dense_mma_kernel<512, 128, true>,  cudaFuncAttributeMaxDynamicSharedMemorySize, SMD);

    const int TB = 256;
    dim3 blk(TB);
    const int gx  = (Nn + 127) / 128;
    const int egx = (E + 127) / 128;

    // launch order puts edge1 at slot 4 (the ncu-profiled launch)
    prep_wb_kernel<<<(64 * 64 + TB - 1) / TB, blk>>>(w1b, wh1, wl1, 64, 64, 64);              // 1
    convert_idx_kernel<<<(E + TB - 1) / TB, blk>>>((const unsigned*)ei, E);                   // 2
    node1_fused_kernel<<<(Nn * 128 + TB - 1) / TB, blk>>>(x, w1a, b1a, AB, agg, Nn);          // 3
    edge_mma_kernel<64, 64, 3><<<dim3(egx, 1), blk, SM1>>>(AB, wh1, wl1, b1b, agg, E, 64);    // 4
    decode_kernel<<<(Nn * 64 + TB - 1) / TB, blk>>>(agg, hcat + 0, Nn * 64, 64, 448);         // 5

    // ---- EdgeConv 2: 64 -> 128 ----
    prep_kernel<<<64, blk>>>(w2a, b2a, wc2, bc2, 64, 128);
    prep_wb_kernel<<<(64 * 256 + TB - 1) / TB, blk>>>(wc2, whn2, wln2, 64, 256, 128);
    prep_wb_kernel<<<(128 * 128 + TB - 1) / TB, blk>>>(w2b, wh2, wl2, 128, 128, 128);
    dense_mma_kernel<64, 128, false><<<dim3(gx, 2), blk, SMD>>>(hcat, 448, whn2, wln2, bc2, AB, 256, Nn);
    clear_kernel<<<(Nn * 128 + TB - 1) / TB, blk>>>(agg, Nn * 128);
    edge_mma_kernel<128, 128, 2><<<dim3(egx, 1), blk, SM2>>>(AB, wh2, wl2, b2b, agg, E, 128);
    decode_kernel<<<(Nn * 128 + TB - 1) / TB, blk>>>(agg, hcat + 64, Nn * 128, 128, 448);

    // ---- EdgeConv 3: 128 -> 256 ----
    prep_kernel<<<256, blk>>>(w3a, b3a, wc3, bc3, 128, 256);
    prep_wb_kernel<<<(128 * 512 + TB - 1) / TB, blk>>>(wc3, whn3, wln3, 128, 512, 128);
    prep_wb_kernel<<<(256 * 256 + TB - 1) / TB, blk>>>(w3b, wh3, wl3, 256, 256, 128);
    dense_mma_kernel<128, 128, false><<<dim3(gx, 4), blk, SMD>>>(hcat + 64, 448, whn3, wln3, bc3, AB, 512, Nn);
    clear_kernel<<<(Nn * 256 + TB - 1) / TB, blk>>>(agg, Nn * 256);
    edge_mma_kernel<256, 128, 2><<<dim3(egx, 2), blk, SM2>>>(AB, wh3, wl3, b3b, agg, E, 256);
    decode_kernel<<<(Nn * 256 + TB - 1) / TB, blk>>>(agg, hcat + 192, Nn * 256, 256, 448);

    // ---- MLP head ----
    prep_wb_kernel<<<(448 * 512 + TB - 1) / TB, blk>>>(wm1, whm1, wlm1, 448, 512, 128);
    dense_mma_kernel<448, 128, true><<<dim3(gx, 4), blk, SMD>>>(hcat, 448, whm1, wlm1, bm1, m1, 512, Nn);
    prep_wb_kernel<<<(512 * 256 + TB - 1) / TB, blk>>>(wm2, whm2, wlm2, 512, 256, 128);
    dense_mma_kernel<512, 128, true><<<dim3(gx, 2), blk, SMD>>>(m1, 512, whm2, wlm2, bm2, m2, 256, Nn);
    mlp3_kernel<<<(Nn * 32 + TB - 1) / TB, blk>>>(m2, wm3, bm3, out, Nn);
}

// round 8
// speedup vs baseline: 2.4731x; 1.1935x over previous
#include <cuda_runtime.h>
#include <cuda_bf16.h>
#include <cstdint>

// ---------------------------------------------------------------------------
// DGCNN segmentation. ALL GEMMs on tensor cores via mma.sync bf16x3 split
// precision (ldmatrix frags, cp.async.cg W streaming, 64-wide K chunks).
// Edges counting-sorted by dst for gather/atomic locality (max is order-inv).
// ---------------------------------------------------------------------------

#define NMAX 30016
#define EMAX 480256
#define NBIN 30720   // 1024 * 30

__device__ float    g_AB[NMAX * 512];
__device__ unsigned g_agg[NMAX * 256];
__device__ float    g_hcat[NMAX * 448];
__device__ float    g_m1[NMAX * 512];
__device__ float    g_m2[NMAX * 256];
__device__ float    g_wc2[64 * 256];
__device__ float    g_wc3[128 * 512];
__device__ float    g_bc2[256];
__device__ float    g_bc3[512];
__device__ uint4    g_wh1[64 * 72 / 8],       g_wl1[64 * 72 / 8];
__device__ uint4    g_wh2[2 * 128 * 72 / 8],  g_wl2[2 * 128 * 72 / 8];
__device__ uint4    g_wh3[8 * 128 * 72 / 8],  g_wl3[8 * 128 * 72 / 8];
__device__ uint4    g_whn2[2304],  g_wln2[2304];
__device__ uint4    g_whn3[9216],  g_wln3[9216];
__device__ uint4    g_whm1[32256], g_wlm1[32256];
__device__ uint4    g_whm2[18432], g_wlm2[18432];
__device__ int      g_src[EMAX];
__device__ int      g_dst[EMAX];
__device__ int      g_srcS[EMAX];   // sorted by dst
__device__ int      g_dstS[EMAX];
__device__ int      g_cnt[NBIN];
__device__ int      g_c2[NBIN];
__device__ int      g_start[NBIN];

// ---- ordered-uint encoding for float max ------------------------------------
__device__ __forceinline__ unsigned f2ord(float f) {
    int i = __float_as_int(f);
    return (i >= 0) ? ((unsigned)i | 0x80000000u) : ~(unsigned)i;
}
__device__ __forceinline__ float ord2f(unsigned u) {
    int i = (u & 0x80000000u) ? (int)(u & 0x7fffffffu) : (int)(~u);
    return __int_as_float(i);
}

// ---- PTX helpers --------------------------------------------------------------
__device__ __forceinline__ uint32_t smem_u32(const void* p) {
    uint32_t a;
    asm("{ .reg .u64 t; cvta.to.shared.u64 t, %1; cvt.u32.u64 %0, t; }" : "=r"(a) : "l"(p));
    return a;
}
__device__ __forceinline__ void mma_bf16(float* d, const uint32_t* a,
                                         uint32_t b0, uint32_t b1) {
    asm volatile(
        "mma.sync.aligned.m16n8k16.row.col.f32.bf16.bf16.f32 "
        "{%0,%1,%2,%3},{%4,%5,%6,%7},{%8,%9},{%0,%1,%2,%3};"
        : "+f"(d[0]), "+f"(d[1]), "+f"(d[2]), "+f"(d[3])
        : "r"(a[0]), "r"(a[1]), "r"(a[2]), "r"(a[3]), "r"(b0), "r"(b1));
}
__device__ __forceinline__ void ldsm_x4(uint32_t* r, uint32_t addr) {
    asm volatile("ldmatrix.sync.aligned.m8n8.x4.shared.b16 {%0,%1,%2,%3},[%4];"
                 : "=r"(r[0]), "=r"(r[1]), "=r"(r[2]), "=r"(r[3]) : "r"(addr));
}
__device__ __forceinline__ void cp16(uint32_t s, const void* g) {
    asm volatile("cp.async.cg.shared.global [%0],[%1],16;" :: "r"(s), "l"(g));
}
__device__ __forceinline__ void split2(float m0, float m1, uint32_t& hi2, uint32_t& lo2) {
    asm("cvt.rn.bf16x2.f32 %0, %1, %2;" : "=r"(hi2) : "f"(m1), "f"(m0));
    float h0 = __uint_as_float(hi2 << 16);
    float h1 = __uint_as_float(hi2 & 0xffff0000u);
    float l0 = m0 - h0, l1 = m1 - h1;
    asm("cvt.rn.bf16x2.f32 %0, %1, %2;" : "=r"(lo2) : "f"(l1), "f"(l0));
}

// ---- edge index convert (+ zero sort bins) ------------------------------------
__global__ void convert_idx_kernel(const unsigned* __restrict__ raw, int E) {
    int n = (E < 256) ? E : 256;
    int is64 = 1;
    for (int i = 0; i < n; i++)
        if (raw[2 * i + 1] != 0u) { is64 = 0; break; }
    int i = blockIdx.x * blockDim.x + threadIdx.x;
    if (i < NBIN) { g_cnt[i] = 0; g_c2[i] = 0; }
    if (i >= E) return;
    if (is64) {
        const long long* p = (const long long*)raw;
        g_src[i] = (int)p[i];
        g_dst[i] = (int)p[E + i];
    } else {
        const int* p = (const int*)raw;
        g_src[i] = p[i];
        g_dst[i] = p[E + i];
    }
}
__global__ void hist_kernel(int E) {
    int i = blockIdx.x * blockDim.x + threadIdx.x;
    if (i < E) atomicAdd(&g_cnt[g_dst[i]], 1);
}
__global__ void scan_kernel() {   // 1 block, 1024 threads, 30 bins each
    __shared__ int part[1024];
    int t = threadIdx.x;
    int base = t * 30;
    int s = 0;
#pragma unroll
    for (int j = 0; j < 30; j++) s += g_cnt[base + j];
    part[t] = s;
    __syncthreads();
    for (int off = 1; off < 1024; off <<= 1) {
        int v = (t >= off) ? part[t - off] : 0;
        __syncthreads();
        part[t] += v;
        __syncthreads();
    }
    int run = part[t] - s;    // exclusive prefix of this range
#pragma unroll
    for (int j = 0; j < 30; j++) {
        g_start[base + j] = run;
        run += g_cnt[base + j];
    }
}
__global__ void scatter_kernel(int E) {
    int i = blockIdx.x * blockDim.x + threadIdx.x;
    if (i >= E) return;
    int d = g_dst[i];
    int pos = g_start[d] + atomicAdd(&g_c2[d], 1);
    g_srcS[pos] = g_src[i];
    g_dstS[pos] = d;
}

// ---- weight prep: wc = [Wtop - Wbot | Wbot], bc = [b | 0] ---------------------
__global__ void prep_kernel(const float* __restrict__ w, const float* __restrict__ b,
                            float* __restrict__ wc, float* __restrict__ bc,
                            int C, int H) {
    int stride = gridDim.x * blockDim.x;
    int i0 = blockIdx.x * blockDim.x + threadIdx.x;
    for (int t = i0; t < C * H; t += stride) {
        int k = t / H, j = t % H;
        float wd = w[(k + C) * H + j];
        wc[k * 2 * H + j]     = w[k * H + j] - wd;
        wc[k * 2 * H + H + j] = wd;
    }
    for (int t = i0; t < H; t += stride) { bc[t] = b[t]; bc[H + t] = 0.f; }
}

// ---- weight prep: W^T bf16 hi/lo chunked [(tile*NCH+c)*BN + n][72] ------------
__global__ void prep_wb_kernel(const float* __restrict__ W,
                               uint4* __restrict__ Whi, uint4* __restrict__ Wlo,
                               int H, int COUT, int BN) {
    int i = blockIdx.x * blockDim.x + threadIdx.x;
    if (i >= H * COUT) return;
    int k = i / COUT, n = i % COUT;
    float w = W[i];
    __nv_bfloat16 hb = __float2bfloat16(w);
    __nv_bfloat16 lb = __float2bfloat16(w - __bfloat162float(hb));
    int NCH = H >> 6;
    int tile = n / BN, nl = n % BN, c = k >> 6, kl = k & 63;
    size_t off = ((size_t)(tile * NCH + c) * BN + nl) * 72 + kl;
    ((unsigned short*)Whi)[off] = __bfloat16_as_ushort(hb);
    ((unsigned short*)Wlo)[off] = __bfloat16_as_ushort(lb);
}

// ---- layer-1 node precompute fused with wc1 prep + agg clear ------------------
__global__ void node1_fused_kernel(const float* __restrict__ x,
                                   const float* __restrict__ w1a,
                                   const float* __restrict__ b1a,
                                   float* __restrict__ AB,
                                   unsigned* __restrict__ agg, int M) {
    int idx = blockIdx.x * blockDim.x + threadIdx.x;
    if (idx >= M * 128) return;
    if (idx < M * 64) agg[idx] = 0u;
    int n = idx >> 7, j = idx & 127;
    float wk0, wk1, wk2, bb;
    if (j < 64) {
        wk0 = w1a[0 * 64 + j] - w1a[3 * 64 + j];
        wk1 = w1a[1 * 64 + j] - w1a[4 * 64 + j];
        wk2 = w1a[2 * 64 + j] - w1a[5 * 64 + j];
        bb  = b1a[j];
    } else {
        int jj = j - 64;
        wk0 = w1a[3 * 64 + jj];
        wk1 = w1a[4 * 64 + jj];
        wk2 = w1a[5 * 64 + jj];
        bb  = 0.f;
    }
    float x0 = x[n * 3 + 0], x1 = x[n * 3 + 1], x2 = x[n * 3 + 2];
    AB[idx] = fmaf(x0, wk0, fmaf(x1, wk1, fmaf(x2, wk2, bb)));
}

// ---- dense bf16x3 mma GEMM: C = act(A[M,K] @ W[K,N] + bias) -------------------
template <int K, int BN, bool RELU>
__global__ void __launch_bounds__(256, 2)
dense_mma_kernel(const float* __restrict__ A, int lda,
                 const uint4* __restrict__ Whi_g, const uint4* __restrict__ Wlo_g,
                 const float* __restrict__ bias,
                 float* __restrict__ C, int ldc, int M) {
    constexpr int NCH = K / 64;
    constexpr int NA  = BN / 16;
    constexpr int WSZ = BN * 144;
    constexpr int ASZ = 128 * 144;
    constexpr int OA  = 2 * WSZ;
    constexpr int WCNT = BN * 9;

    extern __shared__ char sm[];
    const uint32_t smb = smem_u32(sm);

    const int tid = threadIdx.x;
    const int wid = tid >> 5, lane = tid & 31;
    const int g = lane >> 2, tig = lane & 3;
    const int bm = blockIdx.x * 128;
    const int bn = blockIdx.y * BN;

    const int r  = tid >> 1;
    const int hf = tid & 1;
    const bool rv = (bm + r) < M;
    const float* Arow = A + (size_t)(bm + r) * lda + hf * 32;

    const int wm = wid >> 1, wn = wid & 1;
    const int m0 = wm * 32, n0 = wn * (BN / 2);

    const int lr = lane & 7;
    const uint32_t a_off =
        (uint32_t)(m0 + lr + ((lane >> 3) & 1) * 8) * 144u + (uint32_t)(lane >> 4) * 16u;
    const uint32_t w_off =
        (uint32_t)(n0 + lr + ((lane >> 4) & 1) * 8) * 144u + (uint32_t)((lane >> 3) & 1) * 16u;

    const uint32_t WhU = smb;
    const uint32_t WlU = WhU + WSZ;
    const uint32_t AhU = smb + OA;
    const uint32_t AlU = AhU + ASZ;
    char* Ah = sm + OA;
    char* Al = sm + OA + ASZ;

    float acc[2][NA][4];
#pragma unroll
    for (int ma = 0; ma < 2; ma++)
#pragma unroll
        for (int na = 0; na < NA; na++)
#pragma unroll
            for (int q = 0; q < 4; q++) acc[ma][na][q] = 0.f;

    for (int c = 0; c < NCH; c++) {
        if (c) __syncthreads();
        {
            const char* shp = (const char*)(Whi_g + (size_t)(blockIdx.y * NCH + c) * WCNT);
            const char* slp = (const char*)(Wlo_g + (size_t)(blockIdx.y * NCH + c) * WCNT);
            for (int i = tid; i < WCNT; i += 256) {
                cp16(WhU + i * 16, shp + i * 16);
                cp16(WlU + i * 16, slp + i * 16);
            }
            asm volatile("cp.async.commit_group;" ::: "memory");
        }
        {
            const float4* Ap = (const float4*)(Arow + c * 64);
            float v[32];
            if (rv) {
#pragma unroll
                for (int q = 0; q < 8; q++) {
                    float4 a = Ap[q];
                    v[q * 4 + 0] = a.x; v[q * 4 + 1] = a.y;
                    v[q * 4 + 2] = a.z; v[q * 4 + 3] = a.w;
                }
            } else {
#pragma unroll
                for (int q = 0; q < 32; q++) v[q] = 0.f;
            }
            char* ah = Ah + r * 144 + hf * 64;
            char* al = Al + r * 144 + hf * 64;
#pragma unroll
            for (int q8 = 0; q8 < 4; q8++) {
                uint32_t uh[4], ul[4];
#pragma unroll
                for (int p = 0; p < 4; p++)
                    split2(v[q8 * 8 + p * 2], v[q8 * 8 + p * 2 + 1], uh[p], ul[p]);
                *(uint4*)(ah + q8 * 16) = make_uint4(uh[0], uh[1], uh[2], uh[3]);
                *(uint4*)(al + q8 * 16) = make_uint4(ul[0], ul[1], ul[2], ul[3]);
            }
        }
        asm volatile("cp.async.wait_group 0;" ::: "memory");
        __syncthreads();

#pragma unroll
        for (int kq = 0; kq < 4; kq++) {
            uint32_t ah[2][4], al[2][4];
#pragma unroll
            for (int ma = 0; ma < 2; ma++) {
                ldsm_x4(ah[ma], AhU + a_off + (uint32_t)(ma * 16 * 144 + kq * 32));
                ldsm_x4(al[ma], AlU + a_off + (uint32_t)(ma * 16 * 144 + kq * 32));
            }
#pragma unroll
            for (int n2 = 0; n2 < NA / 2; n2++) {
                uint32_t wh[4], wl[4];
                ldsm_x4(wh, WhU + w_off + (uint32_t)(n2 * 16 * 144 + kq * 32));
                ldsm_x4(wl, WlU + w_off + (uint32_t)(n2 * 16 * 144 + kq * 32));
#pragma unroll
                for (int j = 0; j < 2; j++) {
                    const int na = n2 * 2 + j;
                    mma_bf16(acc[0][na], ah[0], wh[2 * j], wh[2 * j + 1]);
                    mma_bf16(acc[1][na], ah[1], wh[2 * j], wh[2 * j + 1]);
                    mma_bf16(acc[0][na], al[0], wh[2 * j], wh[2 * j + 1]);
                    mma_bf16(acc[1][na], al[1], wh[2 * j], wh[2 * j + 1]);
                    mma_bf16(acc[0][na], ah[0], wl[2 * j], wl[2 * j + 1]);
                    mma_bf16(acc[1][na], ah[1], wl[2 * j], wl[2 * j + 1]);
                }
            }
        }
    }

#pragma unroll
    for (int ma = 0; ma < 2; ma++) {
#pragma unroll
        for (int rr = 0; rr < 2; rr++) {
            const int rg = bm + m0 + ma * 16 + g + rr * 8;
            if (rg >= M) continue;
            float* crow = C + (size_t)rg * ldc + bn;
#pragma unroll
            for (int na = 0; na < NA; na++) {
                const int j = n0 + na * 8 + 2 * tig;
                float v0 = acc[ma][na][rr * 2 + 0] + bias[bn + j];
                float v1 = acc[ma][na][rr * 2 + 1] + bias[bn + j + 1];
                if (RELU) { v0 = fmaxf(v0, 0.f); v1 = fmaxf(v1, 0.f); }
                *(float2*)(crow + j) = make_float2(v0, v1);
            }
        }
    }
}

// ---- mma.sync edge kernel: sorted edges, B-side register prefetch -------------
template <int H, int BN, int MINB>
__global__ void __launch_bounds__(256, MINB)
edge_mma_kernel(const float* __restrict__ AB,
                const uint4* __restrict__ Whi_g, const uint4* __restrict__ Wlo_g,
                const float* __restrict__ bias,
                unsigned* __restrict__ agg, int E, int COUT) {
    constexpr int NCH = H / 64;
    constexpr int NA  = BN / 16;
    constexpr int WSZ = BN * 144;
    constexpr int ASZ = 128 * 144;
    constexpr int OW  = 1024;
    constexpr int OA  = OW + 2 * WSZ;
    constexpr int WCNT = BN * 9;

    extern __shared__ char sm[];
    const uint32_t smb = smem_u32(sm);
    int* sdst = (int*)sm;
    int* ssrc = (int*)(sm + 512);

    const int tid = threadIdx.x;
    const int wid = tid >> 5, lane = tid & 31;
    const int g = lane >> 2, tig = lane & 3;
    const int e0 = blockIdx.x * 128;
    const int bn = blockIdx.y * BN;

    if (tid < 128) { int e = e0 + tid; ssrc[tid] = (e < E) ? g_srcS[e] : 0; }
    else           { int e = e0 + tid - 128; sdst[tid - 128] = (e < E) ? g_dstS[e] : 0; }
    __syncthreads();

    const int r  = tid >> 1;
    const int hf = tid & 1;
    const float* Arow = AB + (size_t)sdst[r] * (2 * H) + hf * 32;
    const float* Brow = AB + (size_t)ssrc[r] * (2 * H) + H + hf * 32;

    const int wm = wid >> 1, wn = wid & 1;
    const int m0 = wm * 32, n0 = wn * (BN / 2);

    const int lr = lane & 7;
    const uint32_t a_off =
        (uint32_t)(m0 + lr + ((lane >> 3) & 1) * 8) * 144u + (uint32_t)(lane >> 4) * 16u;
    const uint32_t w_off =
        (uint32_t)(n0 + lr + ((lane >> 4) & 1) * 8) * 144u + (uint32_t)((lane >> 3) & 1) * 16u;

    const uint32_t WhU = smb + OW;
    const uint32_t WlU = WhU + WSZ;
    const uint32_t AhU = smb + OA;
    const uint32_t AlU = AhU + ASZ;
    char* Ah = sm + OA;
    char* Al = sm + OA + ASZ;

    float acc[2][NA][4];
#pragma unroll
    for (int ma = 0; ma < 2; ma++)
#pragma unroll
        for (int na = 0; na < NA; na++)
#pragma unroll
            for (int q = 0; q < 4; q++) acc[ma][na][q] = 0.f;

    // prefetch B-side (random src gather) for chunk 0
    float4 pre[4];
#pragma unroll
    for (int q = 0; q < 4; q++) pre[q] = ((const float4*)Brow)[q];

    for (int c = 0; c < NCH; c++) {
        if (c) __syncthreads();
        {
            const char* shp = (const char*)(Whi_g + (size_t)(blockIdx.y * NCH + c) * WCNT);
            const char* slp = (const char*)(Wlo_g + (size_t)(blockIdx.y * NCH + c) * WCNT);
            for (int i = tid; i < WCNT; i += 256) {
                cp16(WhU + i * 16, shp + i * 16);
                cp16(WlU + i * 16, slp + i * 16);
            }
            asm volatile("cp.async.commit_group;" ::: "memory");
        }
        {
            const float4* Ap = (const float4*)(Arow + c * 64);
            const float4* Bp = (const float4*)(Brow + c * 64);
            float v[32];
#pragma unroll
            for (int q = 0; q < 4; q++) {          // first half from prefetch regs
                float4 a = Ap[q], b = pre[q];
                v[q * 4 + 0] = fmaxf(a.x + b.x, 0.f);
                v[q * 4 + 1] = fmaxf(a.y + b.y, 0.f);
                v[q * 4 + 2] = fmaxf(a.z + b.z, 0.f);
                v[q * 4 + 3] = fmaxf(a.w + b.w, 0.f);
            }
#pragma unroll
            for (int q = 4; q < 8; q++) {          // second half direct
                float4 a = Ap[q], b = Bp[q];
                v[q * 4 + 0] = fmaxf(a.x + b.x, 0.f);
                v[q * 4 + 1] = fmaxf(a.y + b.y, 0.f);
                v[q * 4 + 2] = fmaxf(a.z + b.z, 0.f);
                v[q * 4 + 3] = fmaxf(a.w + b.w, 0.f);
            }
            if (c + 1 < NCH) {                     // prefetch next chunk's B first half
                const float4* Bn = (const float4*)(Brow + (c + 1) * 64);
#pragma unroll
                for (int q = 0; q < 4; q++) pre[q] = Bn[q];
            }
            char* ah = Ah + r * 144 + hf * 64;
            char* al = Al + r * 144 + hf * 64;
#pragma unroll
            for (int q8 = 0; q8 < 4; q8++) {
                uint32_t uh[4], ul[4];
#pragma unroll
                for (int p = 0; p < 4; p++)
                    split2(v[q8 * 8 + p * 2], v[q8 * 8 + p * 2 + 1], uh[p], ul[p]);
                *(uint4*)(ah + q8 * 16) = make_uint4(uh[0], uh[1], uh[2], uh[3]);
                *(uint4*)(al + q8 * 16) = make_uint4(ul[0], ul[1], ul[2], ul[3]);
            }
        }
        asm volatile("cp.async.wait_group 0;" ::: "memory");
        __syncthreads();

#pragma unroll
        for (int kq = 0; kq < 4; kq++) {
            uint32_t ah[2][4], al[2][4];
#pragma unroll
            for (int ma = 0; ma < 2; ma++) {
                ldsm_x4(ah[ma], AhU + a_off + (uint32_t)(ma * 16 * 144 + kq * 32));
                ldsm_x4(al[ma], AlU + a_off + (uint32_t)(ma * 16 * 144 + kq * 32));
            }
#pragma unroll
            for (int n2 = 0; n2 < NA / 2; n2++) {
                uint32_t wh[4], wl[4];
                ldsm_x4(wh, WhU + w_off + (uint32_t)(n2 * 16 * 144 + kq * 32));
                ldsm_x4(wl, WlU + w_off + (uint32_t)(n2 * 16 * 144 + kq * 32));
#pragma unroll
                for (int j = 0; j < 2; j++) {
                    const int na = n2 * 2 + j;
                    mma_bf16(acc[0][na], ah[0], wh[2 * j], wh[2 * j + 1]);
                    mma_bf16(acc[1][na], ah[1], wh[2 * j], wh[2 * j + 1]);
                    mma_bf16(acc[0][na], al[0], wh[2 * j], wh[2 * j + 1]);
                    mma_bf16(acc[1][na], al[1], wh[2 * j], wh[2 * j + 1]);
                    mma_bf16(acc[0][na], ah[0], wl[2 * j], wl[2 * j + 1]);
                    mma_bf16(acc[1][na], ah[1], wl[2 * j], wl[2 * j + 1]);
                }
            }
        }
    }

    // ---- epilogue: bias + stale-safe guard + atomicMax ----
#pragma unroll
    for (int ma = 0; ma < 2; ma++) {
#pragma unroll
        for (int rr = 0; rr < 2; rr++) {
            const int rloc = m0 + ma * 16 + g + rr * 8;
            if (e0 + rloc >= E) continue;
            const int d = sdst[rloc];
            unsigned* arow = agg + (size_t)d * COUT + bn;
#pragma unroll
            for (int na = 0; na < NA; na++) {
                const int j = n0 + na * 8 + 2 * tig;
                float v0 = acc[ma][na][rr * 2 + 0] + bias[bn + j];
                float v1 = acc[ma][na][rr * 2 + 1] + bias[bn + j + 1];
                unsigned k0 = f2ord(v0);
                unsigned k1 = f2ord(v1);
                uint2 cur = *(const uint2*)(arow + j);
                if (k0 > cur.x) atomicMax(arow + j, k0);
                if (k1 > cur.y) atomicMax(arow + j + 1, k1);
            }
        }
    }
}

// ---- decode agg -> float -------------------------------------------------------
__global__ void decode_kernel(const unsigned* __restrict__ agg,
                              float* __restrict__ dsth, int total, int C, int ldc) {
    int i = blockIdx.x * blockDim.x + threadIdx.x;
    if (i >= total) return;
    int n = i / C, c = i % C;
    unsigned u = agg[i];
    dsth[(size_t)n * ldc + c] = (u == 0u) ? 0.f : ord2f(u);
}
__global__ void clear_kernel(unsigned* __restrict__ p, int n) {
    int i = blockIdx.x * blockDim.x + threadIdx.x;
    if (i < n) p[i] = 0u;
}

// ---- final 256 -> 4 linear ------------------------------------------------------
__global__ void mlp3_kernel(const float* __restrict__ A, const float* __restrict__ W,
                            const float* __restrict__ b, float* __restrict__ out, int M) {
    int gw = (blockIdx.x * blockDim.x + threadIdx.x) >> 5;
    int lane = threadIdx.x & 31;
    if (gw >= M) return;
    const float* a = A + (size_t)gw * 256;
    float acc0 = 0.f, acc1 = 0.f, acc2 = 0.f, acc3 = 0.f;
    for (int k = lane; k < 256; k += 32) {
        float av = a[k];
        const float* wr = W + k * 4;
        acc0 = fmaf(av, wr[0], acc0);
        acc1 = fmaf(av, wr[1], acc1);
        acc2 = fmaf(av, wr[2], acc2);
        acc3 = fmaf(av, wr[3], acc3);
    }
#pragma unroll
    for (int off = 16; off > 0; off >>= 1) {
        acc0 += __shfl_down_sync(0xffffffffu, acc0, off);
        acc1 += __shfl_down_sync(0xffffffffu, acc1, off);
        acc2 += __shfl_down_sync(0xffffffffu, acc2, off);
        acc3 += __shfl_down_sync(0xffffffffu, acc3, off);
    }
    if (lane == 0) {
        out[gw * 4 + 0] = acc0 + b[0];
        out[gw * 4 + 1] = acc1 + b[1];
        out[gw * 4 + 2] = acc2 + b[2];
        out[gw * 4 + 3] = acc3 + b[3];
    }
}

// ---------------------------------------------------------------------------
extern "C" void kernel_launch(void* const* d_in, const int* in_sizes, int n_in,
                              void* d_out, int out_size) {
    const float* x   = (const float*)d_in[0];
    const void*  ei  = d_in[1];
    const float* w1a = (const float*)d_in[3];
    const float* b1a = (const float*)d_in[4];
    const float* w1b = (const float*)d_in[5];
    const float* b1b = (const float*)d_in[6];
    const float* w2a = (const float*)d_in[7];
    const float* b2a = (const float*)d_in[8];
    const float* w2b = (const float*)d_in[9];
    const float* b2b = (const float*)d_in[10];
    const float* w3a = (const float*)d_in[11];
    const float* b3a = (const float*)d_in[12];
    const float* w3b = (const float*)d_in[13];
    const float* b3b = (const float*)d_in[14];
    const float* wm1 = (const float*)d_in[15];
    const float* bm1 = (const float*)d_in[16];
    const float* wm2 = (const float*)d_in[17];
    const float* bm2 = (const float*)d_in[18];
    const float* wm3 = (const float*)d_in[19];
    const float* bm3 = (const float*)d_in[20];

    const int Nn = in_sizes[0] / 3;
    const int E  = in_sizes[1] / 2;
    float* out = (float*)d_out;

    float *AB, *hcat, *m1, *m2, *wc2, *wc3, *bc2, *bc3;
    unsigned* agg;
    uint4 *wh1, *wl1, *wh2, *wl2, *wh3, *wl3;
    uint4 *whn2, *wln2, *whn3, *wln3, *whm1, *wlm1, *whm2, *wlm2;
    cudaGetSymbolAddress((void**)&AB,   g_AB);
    cudaGetSymbolAddress((void**)&agg,  g_agg);
    cudaGetSymbolAddress((void**)&hcat, g_hcat);
    cudaGetSymbolAddress((void**)&m1,   g_m1);
    cudaGetSymbolAddress((void**)&m2,   g_m2);
    cudaGetSymbolAddress((void**)&wc2,  g_wc2);
    cudaGetSymbolAddress((void**)&wc3,  g_wc3);
    cudaGetSymbolAddress((void**)&bc2,  g_bc2);
    cudaGetSymbolAddress((void**)&bc3,  g_bc3);
    cudaGetSymbolAddress((void**)&wh1,  g_wh1);
    cudaGetSymbolAddress((void**)&wl1,  g_wl1);
    cudaGetSymbolAddress((void**)&wh2,  g_wh2);
    cudaGetSymbolAddress((void**)&wl2,  g_wl2);
    cudaGetSymbolAddress((void**)&wh3,  g_wh3);
    cudaGetSymbolAddress((void**)&wl3,  g_wl3);
    cudaGetSymbolAddress((void**)&whn2, g_whn2);
    cudaGetSymbolAddress((void**)&wln2, g_wln2);
    cudaGetSymbolAddress((void**)&whn3, g_whn3);
    cudaGetSymbolAddress((void**)&wln3, g_wln3);
    cudaGetSymbolAddress((void**)&whm1, g_whm1);
    cudaGetSymbolAddress((void**)&wlm1, g_wlm1);
    cudaGetSymbolAddress((void**)&whm2, g_whm2);
    cudaGetSymbolAddress((void**)&wlm2, g_wlm2);

    const int SM1 = 1024 + 2 * (64  * 144) + 2 * 18432;  // 56320
    const int SM2 = 1024 + 2 * (128 * 144) + 2 * 18432;  // 74752
    const int SMD = 2 * (128 * 144) + 2 * 18432;         // 73728
    cudaFuncSetAttribute(edge_mma_kernel<64, 64, 3>,   cudaFuncAttributeMaxDynamicSharedMemorySize, SM1);
    cudaFuncSetAttribute(edge_mma_kernel<128, 128, 2>, cudaFuncAttributeMaxDynamicSharedMemorySize, SM2);
    cudaFuncSetAttribute(edge_mma_kernel<256, 128, 2>, cudaFuncAttributeMaxDynamicSharedMemorySize, SM2);
    cudaFuncSetAttribute(dense_mma_kernel<64,  128, false>, cudaFuncAttributeMaxDynamicSharedMemorySize, SMD);
    cudaFuncSetAttribute(dense_mma_kernel<128, 128, false>, cudaFuncAttributeMaxDynamicSharedMemorySize, SMD);
    cudaFuncSetAttribute(dense_mma_kernel<448, 128, true>,  cudaFuncAttributeMaxDynamicSharedMemorySize, SMD);
    cudaFuncSetAttribute(dense_mma_kernel<512, 128, true>,  cudaFuncAttributeMaxDynamicSharedMemorySize, SMD);

    const int TB = 256;
    dim3 blk(TB);
    const int gx  = (Nn + 127) / 128;
    const int egx = (E + 127) / 128;

    // ---- edge sort by dst (counting sort; segment-max is order-invariant) ----
    convert_idx_kernel<<<(E + TB - 1) / TB, blk>>>((const unsigned*)ei, E);
    hist_kernel<<<(E + TB - 1) / TB, blk>>>(E);
    scan_kernel<<<1, 1024>>>();
    scatter_kernel<<<(E + TB - 1) / TB, blk>>>(E);

    // ---- EdgeConv 1: 3 -> 64 ----
    prep_wb_kernel<<<(64 * 64 + TB - 1) / TB, blk>>>(w1b, wh1, wl1, 64, 64, 64);
    node1_fused_kernel<<<(Nn * 128 + TB - 1) / TB, blk>>>(x, w1a, b1a, AB, agg, Nn);
    edge_mma_kernel<64, 64, 3><<<dim3(egx, 1), blk, SM1>>>(AB, wh1, wl1, b1b, agg, E, 64);
    decode_kernel<<<(Nn * 64 + TB - 1) / TB, blk>>>(agg, hcat + 0, Nn * 64, 64, 448);

    // ---- EdgeConv 2: 64 -> 128 ----
    prep_kernel<<<64, blk>>>(w2a, b2a, wc2, bc2, 64, 128);
    prep_wb_kernel<<<(64 * 256 + TB - 1) / TB, blk>>>(wc2, whn2, wln2, 64, 256, 128);
    prep_wb_kernel<<<(128 * 128 + TB - 1) / TB, blk>>>(w2b, wh2, wl2, 128, 128, 128);
    dense_mma_kernel<64, 128, false><<<dim3(gx, 2), blk, SMD>>>(hcat, 448, whn2, wln2, bc2, AB, 256, Nn);
    clear_kernel<<<(Nn * 128 + TB - 1) / TB, blk>>>(agg, Nn * 128);
    edge_mma_kernel<128, 128, 2><<<dim3(egx, 1), blk, SM2>>>(AB, wh2, wl2, b2b, agg, E, 128);
    decode_kernel<<<(Nn * 128 + TB - 1) / TB, blk>>>(agg, hcat + 64, Nn * 128, 128, 448);

    // ---- EdgeConv 3: 128 -> 256 ----
    prep_kernel<<<256, blk>>>(w3a, b3a, wc3, bc3, 128, 256);
    prep_wb_kernel<<<(128 * 512 + TB - 1) / TB, blk>>>(wc3, whn3, wln3, 128, 512, 128);
    prep_wb_kernel<<<(256 * 256 + TB - 1) / TB, blk>>>(w3b, wh3, wl3, 256, 256, 128);
    dense_mma_kernel<128, 128, false><<<dim3(gx, 4), blk, SMD>>>(hcat + 64, 448, whn3, wln3, bc3, AB, 512, Nn);
    clear_kernel<<<(Nn * 256 + TB - 1) / TB, blk>>>(agg, Nn * 256);
    edge_mma_kernel<256, 128, 2><<<dim3(egx, 2), blk, SM2>>>(AB, wh3, wl3, b3b, agg, E, 256);
    decode_kernel<<<(Nn * 256 + TB - 1) / TB, blk>>>(agg, hcat + 192, Nn * 256, 256, 448);

    // ---- MLP head ----
    prep_wb_kernel<<<(448 * 512 + TB - 1) / TB, blk>>>(wm1, whm1, wlm1, 448, 512, 128);
    dense_mma_kernel<448, 128, true><<<dim3(gx, 4), blk, SMD>>>(hcat, 448, whm1, wlm1, bm1, m1, 512, Nn);
    prep_wb_kernel<<<(512 * 256 + TB - 1) / TB, blk>>>(wm2, whm2, wlm2, 512, 256, 128);
    dense_mma_kernel<512, 128, true><<<dim3(gx, 2), blk, SMD>>>(m1, 512, whm2, wlm2, bm2, m2, 256, Nn);
    mlp3_kernel<<<(Nn * 32 + TB - 1) / TB, blk>>>(m2, wm3, bm3, out, Nn);
}